// round 1
// baseline (speedup 1.0000x reference)
#include <cuda_runtime.h>

#define HEADS 16
#define HD 16
#define NW 64          // tokens per window
#define CH 256         // channels
#define P1 257         // pitch (floats) for 64x256 buffers -> bank (n+c)%32
#define PQ 17          // pitch for 64x16 head tiles

// Precomputed relative-position bias, expanded per head: [16][64][64]
__device__ float g_bias[HEADS * NW * NW];

__global__ void bias_precompute(const float* __restrict__ table,
                                const int* __restrict__ ridx) {
    int t = blockIdx.x * blockDim.x + threadIdx.x;  // h*4096 + i*64 + j
    if (t < HEADS * NW * NW) {
        int h = t >> 12;
        int ij = t & 4095;
        g_bias[t] = table[ridx[ij] * HEADS + h];
    }
}

__global__ __launch_bounds__(256, 1)
void window_attn_kernel(const float* __restrict__ X,
                        const float* __restrict__ pre_g, const float* __restrict__ pre_b,
                        const float* __restrict__ post_g, const float* __restrict__ post_b,
                        const float* __restrict__ qkv_w, const float* __restrict__ qkv_b,
                        const float* __restrict__ proj_w, const float* __restrict__ proj_b,
                        float* __restrict__ out) {
    extern __shared__ float sm[];
    float* s_x  = sm;                 // [64][257] raw window (residual)
    float* s_n  = s_x + NW * P1;      // [64][257] LN output / later t = x+attn
    float* s_o  = s_n + NW * P1;      // [64][257] attention head-concat output
    float* s_q  = s_o + NW * P1;      // [64][17]
    float* s_k  = s_q + NW * PQ;      // [64][17]
    float* s_v  = s_k + NW * PQ;      // [64][17]
    float* s_pg = s_v + NW * PQ;      // 256
    float* s_pb = s_pg + CH;
    float* s_gg = s_pb + CH;
    float* s_gb = s_gg + CH;
    float* s_prb = s_gb + CH;
    float* s_qkvb = s_prb + CH;       // 768
    float* s_m  = s_qkvb + 3 * CH;    // 64
    float* s_i  = s_m + NW;           // 64

    const int w    = blockIdx.x;
    const int b    = w >> 10;
    const int hi   = (w >> 5) & 31;
    const int wi   = w & 31;
    const int tid  = threadIdx.x;
    const int lane = tid & 31;
    const int warp = tid >> 5;

    // base of this window in [B,C,H,W]; per-channel plane stride = 65536 floats
    const float* Xb = X + (size_t)b * (CH * 256 * 256) + hi * 8 * 256 + wi * 8;
    float*       Ob = out + (size_t)b * (CH * 256 * 256) + hi * 8 * 256 + wi * 8;

    // ---------- stage 0: load window + small params ----------
    #pragma unroll 8
    for (int i = 0; i < 64; i++) {
        int idx = tid + i * 256;
        int ch  = idx >> 6;
        int n   = idx & 63;
        s_x[n * P1 + ch] = Xb[ch * 65536 + (n >> 3) * 256 + (n & 7)];
    }
    s_pg[tid]  = pre_g[tid];
    s_pb[tid]  = pre_b[tid];
    s_gg[tid]  = post_g[tid];
    s_gb[tid]  = post_b[tid];
    s_prb[tid] = proj_b[tid];
    s_qkvb[tid]       = qkv_b[tid];
    s_qkvb[tid + 256] = qkv_b[tid + 256];
    s_qkvb[tid + 512] = qkv_b[tid + 512];
    __syncthreads();

    // ---------- stage 1: pre-LayerNorm (warp per token row) ----------
    for (int n = warp; n < NW; n += 8) {
        float s = 0.f, s2 = 0.f;
        #pragma unroll
        for (int j = lane; j < CH; j += 32) {
            float v = s_x[n * P1 + j];
            s += v; s2 += v * v;
        }
        #pragma unroll
        for (int o = 16; o; o >>= 1) {
            s  += __shfl_xor_sync(0xffffffffu, s,  o);
            s2 += __shfl_xor_sync(0xffffffffu, s2, o);
        }
        float m   = s * (1.f / 256.f);
        float inv = rsqrtf(s2 * (1.f / 256.f) - m * m + 1e-5f);
        #pragma unroll
        for (int j = lane; j < CH; j += 32) {
            float v = s_x[n * P1 + j];
            s_n[n * P1 + j] = (v - m) * inv * s_pg[j] + s_pb[j];
        }
    }
    __syncthreads();

    const int nrow = tid >> 2;   // token row 0..63
    const int dg   = tid & 3;    // quarter within hd / j-group
    const float* __restrict__ xrow = s_n + nrow * P1;

    // ---------- stage 2: per-head attention ----------
    for (int h = 0; h < HEADS; h++) {
        // --- 2a: qkv for this head. thread -> token nrow, cols dg*4..dg*4+3 ---
        float aq[4] = {0, 0, 0, 0}, ak[4] = {0, 0, 0, 0}, av[4] = {0, 0, 0, 0};
        const float* wq = qkv_w + h * 16 + dg * 4;
        #pragma unroll 4
        for (int k = 0; k < CH; k++) {
            float x = xrow[k];
            float4 q4 = *(const float4*)(wq + k * 768);
            float4 k4 = *(const float4*)(wq + k * 768 + 256);
            float4 v4 = *(const float4*)(wq + k * 768 + 512);
            aq[0] = fmaf(x, q4.x, aq[0]); aq[1] = fmaf(x, q4.y, aq[1]);
            aq[2] = fmaf(x, q4.z, aq[2]); aq[3] = fmaf(x, q4.w, aq[3]);
            ak[0] = fmaf(x, k4.x, ak[0]); ak[1] = fmaf(x, k4.y, ak[1]);
            ak[2] = fmaf(x, k4.z, ak[2]); ak[3] = fmaf(x, k4.w, ak[3]);
            av[0] = fmaf(x, v4.x, av[0]); av[1] = fmaf(x, v4.y, av[1]);
            av[2] = fmaf(x, v4.z, av[2]); av[3] = fmaf(x, v4.w, av[3]);
        }
        int cb0 = h * 16 + dg * 4;
        #pragma unroll
        for (int j = 0; j < 4; j++) {
            aq[j] += s_qkvb[cb0 + j];
            ak[j] += s_qkvb[256 + cb0 + j];
            av[j] += s_qkvb[512 + cb0 + j];
        }
        // l2norm of q,k over hd=16 (4-thread groups share nrow)
        float sq = aq[0]*aq[0] + aq[1]*aq[1] + aq[2]*aq[2] + aq[3]*aq[3];
        float sk = ak[0]*ak[0] + ak[1]*ak[1] + ak[2]*ak[2] + ak[3]*ak[3];
        sq += __shfl_xor_sync(0xffffffffu, sq, 1);
        sq += __shfl_xor_sync(0xffffffffu, sq, 2);
        sk += __shfl_xor_sync(0xffffffffu, sk, 1);
        sk += __shfl_xor_sync(0xffffffffu, sk, 2);
        float rq = 1.f / fmaxf(sqrtf(sq), 1e-12f);
        float rk = 1.f / fmaxf(sqrtf(sk), 1e-12f);
        float* qp = s_q + nrow * PQ + dg * 4;
        float* kp = s_k + nrow * PQ + dg * 4;
        float* vp = s_v + nrow * PQ + dg * 4;
        #pragma unroll
        for (int j = 0; j < 4; j++) {
            qp[j] = aq[j] * rq;
            kp[j] = ak[j] * rk;
            vp[j] = av[j];
        }
        __syncthreads();

        // --- 2b: logits S[i=nrow][j = jj*4+dg] + bias, softmax over group, PV ---
        float qreg[16];
        #pragma unroll
        for (int d = 0; d < 16; d++) qreg[d] = s_q[nrow * PQ + d];

        float S[16];
        const float* brow = g_bias + h * 4096 + nrow * 64;
        #pragma unroll
        for (int jj = 0; jj < 16; jj++) {
            int j = jj * 4 + dg;
            const float* kr = s_k + j * PQ;
            float acc = brow[j];
            #pragma unroll
            for (int d = 0; d < 16; d++) acc = fmaf(qreg[d], kr[d], acc);
            S[jj] = acc;
        }
        float mx = S[0];
        #pragma unroll
        for (int jj = 1; jj < 16; jj++) mx = fmaxf(mx, S[jj]);
        mx = fmaxf(mx, __shfl_xor_sync(0xffffffffu, mx, 1));
        mx = fmaxf(mx, __shfl_xor_sync(0xffffffffu, mx, 2));
        float sum = 0.f;
        #pragma unroll
        for (int jj = 0; jj < 16; jj++) { S[jj] = __expf(S[jj] - mx); sum += S[jj]; }
        sum += __shfl_xor_sync(0xffffffffu, sum, 1);
        sum += __shfl_xor_sync(0xffffffffu, sum, 2);
        float rs = 1.f / sum;

        float o[16];
        #pragma unroll
        for (int d = 0; d < 16; d++) o[d] = 0.f;
        #pragma unroll
        for (int jj = 0; jj < 16; jj++) {
            float p = S[jj];
            const float* vr = s_v + (jj * 4 + dg) * PQ;
            #pragma unroll
            for (int d = 0; d < 16; d++) o[d] = fmaf(p, vr[d], o[d]);
        }
        #pragma unroll
        for (int d = 0; d < 16; d++) {
            o[d] += __shfl_xor_sync(0xffffffffu, o[d], 1);
            o[d] += __shfl_xor_sync(0xffffffffu, o[d], 2);
        }
        if (dg == 0) {
            float* op = s_o + nrow * P1 + h * 16;
            #pragma unroll
            for (int d = 0; d < 16; d++) op[d] = o[d] * rs;
        }
        __syncthreads();
    }

    // ---------- stage 3: proj + residual -> t in s_n ----------
    {
        const float* __restrict__ orow = s_o + nrow * P1;
        #pragma unroll
        for (int cb = 0; cb < 4; cb++) {
            int c0 = cb * 64 + dg * 16;
            float a[16];
            #pragma unroll
            for (int j = 0; j < 16; j++) a[j] = s_prb[c0 + j];
            const float* wp = proj_w + c0;
            #pragma unroll 4
            for (int k = 0; k < CH; k++) {
                float x = orow[k];
                float4 w0 = *(const float4*)(wp + k * 256);
                float4 w1 = *(const float4*)(wp + k * 256 + 4);
                float4 w2 = *(const float4*)(wp + k * 256 + 8);
                float4 w3 = *(const float4*)(wp + k * 256 + 12);
                a[0]  = fmaf(x, w0.x, a[0]);  a[1]  = fmaf(x, w0.y, a[1]);
                a[2]  = fmaf(x, w0.z, a[2]);  a[3]  = fmaf(x, w0.w, a[3]);
                a[4]  = fmaf(x, w1.x, a[4]);  a[5]  = fmaf(x, w1.y, a[5]);
                a[6]  = fmaf(x, w1.z, a[6]);  a[7]  = fmaf(x, w1.w, a[7]);
                a[8]  = fmaf(x, w2.x, a[8]);  a[9]  = fmaf(x, w2.y, a[9]);
                a[10] = fmaf(x, w2.z, a[10]); a[11] = fmaf(x, w2.w, a[11]);
                a[12] = fmaf(x, w3.x, a[12]); a[13] = fmaf(x, w3.y, a[13]);
                a[14] = fmaf(x, w3.z, a[14]); a[15] = fmaf(x, w3.w, a[15]);
            }
            #pragma unroll
            for (int j = 0; j < 16; j++)
                s_n[nrow * P1 + c0 + j] = s_x[nrow * P1 + c0 + j] + a[j];
        }
    }
    __syncthreads();

    // ---------- stage 4a: post-LN stats on t ----------
    for (int n = warp; n < NW; n += 8) {
        float s = 0.f, s2 = 0.f;
        #pragma unroll
        for (int j = lane; j < CH; j += 32) {
            float v = s_n[n * P1 + j];
            s += v; s2 += v * v;
        }
        #pragma unroll
        for (int o = 16; o; o >>= 1) {
            s  += __shfl_xor_sync(0xffffffffu, s,  o);
            s2 += __shfl_xor_sync(0xffffffffu, s2, o);
        }
        float m = s * (1.f / 256.f);
        if (lane == 0) {
            s_m[n] = m;
            s_i[n] = rsqrtf(s2 * (1.f / 256.f) - m * m + 1e-5f);
        }
    }
    __syncthreads();

    // ---------- stage 4b: y = t + LN(t)*g + b, scatter back to [B,C,H,W] ----------
    #pragma unroll 8
    for (int i = 0; i < 64; i++) {
        int idx = tid + i * 256;
        int ch  = idx >> 6;
        int n   = idx & 63;
        float v = s_n[n * P1 + ch];
        float y = v + (v - s_m[n]) * s_i[n] * s_gg[ch] + s_gb[ch];
        Ob[ch * 65536 + (n >> 3) * 256 + (n & 7)] = y;
    }
}

extern "C" void kernel_launch(void* const* d_in, const int* in_sizes, int n_in,
                              void* d_out, int out_size) {
    const float* X      = (const float*)d_in[0];
    const float* pre_g  = (const float*)d_in[1];
    const float* pre_b  = (const float*)d_in[2];
    const float* post_g = (const float*)d_in[3];
    const float* post_b = (const float*)d_in[4];
    const float* qkv_w  = (const float*)d_in[5];
    const float* qkv_b  = (const float*)d_in[6];
    const float* proj_w = (const float*)d_in[7];
    const float* proj_b = (const float*)d_in[8];
    const float* rtab   = (const float*)d_in[9];
    const int*   ridx   = (const int*)d_in[10];
    float* out = (float*)d_out;

    const int smem_bytes = (3 * NW * P1 + 3 * NW * PQ + 5 * CH + 3 * CH + 2 * NW) * 4;
    cudaFuncSetAttribute(window_attn_kernel,
                         cudaFuncAttributeMaxDynamicSharedMemorySize, smem_bytes);

    bias_precompute<<<256, 256>>>(rtab, ridx);
    window_attn_kernel<<<2048, 256, smem_bytes>>>(
        X, pre_g, pre_b, post_g, post_b, qkv_w, qkv_b, proj_w, proj_b, out);
}

// round 2
// speedup vs baseline: 4.4190x; 4.4190x over previous
#include <cuda_runtime.h>
#include <cstdint>

#define HEADS 16
#define NW 64
#define CH 256
#define PNT 68     // pitch (m-dim) for transposed [c][m] buffers
#define PC 196     // pitch for qkv C-tile [m][192] and qkv W tile
#define PW2 260    // pitch for proj W tile
#define PT 257     // pitch for s_t [m][256]

// smem float offsets
#define OFF_NT 0        // s_nT: 256*68 = 17408   (aliased later as s_t 64*257)
#define OFF_C  17408    // s_c : 64*196 = 12544   (aliased later as proj W tiles 2*16*260)
#define OFF_OT 29952    // s_oT: 256*68 = 17408
#define OFF_W  47360    // s_w : 2*16*196 = 6272  (aliased as s_bias 4096 during attention)
#define OFF_RQ 53632    // 256
#define OFF_RK 53888    // 256
#define OFF_M  54144    // 64
#define OFF_I  54208    // 64
#define SMEM_FLOATS 54272

__device__ float g_bias[HEADS * NW * NW];

__global__ void bias_precompute(const float* __restrict__ table,
                                const int* __restrict__ ridx) {
    int t = blockIdx.x * blockDim.x + threadIdx.x;
    if (t < HEADS * NW * NW) {
        int h = t >> 12;
        int ij = t & 4095;
        g_bias[t] = table[ridx[ij] * HEADS + h];
    }
}

__device__ __forceinline__ void cp16(const float* dst, const float* src) {
    uint32_t d = (uint32_t)__cvta_generic_to_shared(dst);
    asm volatile("cp.async.ca.shared.global [%0], [%1], 16;" :: "r"(d), "l"(src));
}
__device__ __forceinline__ void cp_commit() { asm volatile("cp.async.commit_group;"); }
__device__ __forceinline__ void cp_wait1()  { asm volatile("cp.async.wait_group 1;"); }
__device__ __forceinline__ void cp_wait0()  { asm volatile("cp.async.wait_group 0;"); }

__global__ __launch_bounds__(256, 1)
void window_attn_kernel(const float* __restrict__ X,
                        const float* __restrict__ pre_g, const float* __restrict__ pre_b,
                        const float* __restrict__ post_g, const float* __restrict__ post_b,
                        const float* __restrict__ qkv_w, const float* __restrict__ qkv_b,
                        const float* __restrict__ proj_w, const float* __restrict__ proj_b,
                        float* __restrict__ out) {
    extern __shared__ float sm[];
    float* s_nT = sm + OFF_NT;   // [256 c][68] LN-out transposed; later s_t
    float* s_c  = sm + OFF_C;    // [64 m][196] qkv tile for 4 heads; later proj W tiles
    float* s_oT = sm + OFF_OT;   // [256 c][68] attention out transposed
    float* s_w  = sm + OFF_W;    // qkv W tiles (double buffered); bias per head
    float* s_rq = sm + OFF_RQ;
    float* s_rk = sm + OFF_RK;
    float* s_m  = sm + OFF_M;
    float* s_i  = sm + OFF_I;
    float* s_t    = s_nT;
    float* s_w2   = s_c;
    float* s_bias = s_w;

    const int w    = blockIdx.x;
    const int b    = w >> 10;
    const int hi   = (w >> 5) & 31;
    const int wi   = w & 31;
    const int tid  = threadIdx.x;
    const int lane = tid & 31;
    const int warp = tid >> 5;

    const float* Xb = X + (size_t)b * (CH * 65536) + hi * 8 * 256 + wi * 8;
    float*       Ob = out + (size_t)b * (CH * 65536) + hi * 8 * 256 + wi * 8;

    // ---------- phase 0: load X window, transposed [c][m] ----------
    #pragma unroll 8
    for (int i = 0; i < 64; i++) {
        int idx = tid + i * 256;
        int ch  = idx >> 6;
        int n   = idx & 63;
        s_nT[ch * PNT + n] = Xb[ch * 65536 + (n >> 3) * 256 + (n & 7)];
    }
    __syncthreads();

    // ---------- phase 1: pre-LN in place (warp per token m) ----------
    for (int m = warp; m < 64; m += 8) {
        float v[8];
        float s = 0.f, s2 = 0.f;
        #pragma unroll
        for (int j = 0; j < 8; j++) {
            v[j] = s_nT[(lane + 32 * j) * PNT + m];
            s += v[j]; s2 += v[j] * v[j];
        }
        #pragma unroll
        for (int o = 16; o; o >>= 1) {
            s  += __shfl_xor_sync(0xffffffffu, s,  o);
            s2 += __shfl_xor_sync(0xffffffffu, s2, o);
        }
        float mean = s * (1.f / 256.f);
        float inv  = rsqrtf(s2 * (1.f / 256.f) - mean * mean + 1e-5f);
        #pragma unroll
        for (int j = 0; j < 8; j++) {
            int c = lane + 32 * j;
            s_nT[c * PNT + m] = (v[j] - mean) * inv * pre_g[c] + pre_b[c];
        }
    }
    __syncthreads();

    const int m0   = (tid >> 5) * 8;       // GEMM m-block (warp-uniform)
    const int n0q  = (tid & 31) * 6;       // qkv n-block
    const int n0p  = (tid & 31) * 8;       // proj n-block
    const int nrow = tid >> 2;             // attention token row
    const int dg   = tid & 3;              // attention column group

    // ---------- phase 2: 4 passes of (qkv GEMM for 4 heads -> attention) ----------
    #pragma unroll 1
    for (int p = 0; p < 4; p++) {
        float acc[48];
        #pragma unroll
        for (int i = 0; i < 48; i++) acc[i] = 0.f;

        // prologue: load W tile for block 0 into buffer 0
        #pragma unroll
        for (int i = 0; i < 3; i++) {
            int idx = tid + i * 256;
            int row = idx / 48;
            int c4  = (idx % 48) * 4;
            int ss  = c4 >> 6, off = c4 & 63;
            cp16(s_w + row * PC + c4, qkv_w + row * 768 + ss * 256 + p * 64 + off);
        }
        cp_commit();

        #pragma unroll 1
        for (int blk = 0; blk < 16; blk++) {
            int bf = blk & 1;
            if (blk < 15) {
                int kb = (blk + 1) * 16;
                #pragma unroll
                for (int i = 0; i < 3; i++) {
                    int idx = tid + i * 256;
                    int row = idx / 48;
                    int c4  = (idx % 48) * 4;
                    int ss  = c4 >> 6, off = c4 & 63;
                    cp16(s_w + ((blk + 1) & 1) * 3136 + row * PC + c4,
                         qkv_w + (kb + row) * 768 + ss * 256 + p * 64 + off);
                }
                cp_commit();
                cp_wait1();
            } else {
                cp_wait0();
            }
            __syncthreads();
            const float* Wb = s_w + bf * 3136;
            #pragma unroll
            for (int kk = 0; kk < 16; kk++) {
                const float* A = s_nT + (blk * 16 + kk) * PNT + m0;
                float4 a0 = *(const float4*)A;
                float4 a1 = *(const float4*)(A + 4);
                const float* Bp = Wb + kk * PC + n0q;
                float b0 = Bp[0], b1 = Bp[1], b2 = Bp[2], b3 = Bp[3], b4 = Bp[4], b5 = Bp[5];
                float av[8] = {a0.x, a0.y, a0.z, a0.w, a1.x, a1.y, a1.z, a1.w};
                #pragma unroll
                for (int i = 0; i < 8; i++) {
                    acc[i*6+0] = fmaf(av[i], b0, acc[i*6+0]);
                    acc[i*6+1] = fmaf(av[i], b1, acc[i*6+1]);
                    acc[i*6+2] = fmaf(av[i], b2, acc[i*6+2]);
                    acc[i*6+3] = fmaf(av[i], b3, acc[i*6+3]);
                    acc[i*6+4] = fmaf(av[i], b4, acc[i*6+4]);
                    acc[i*6+5] = fmaf(av[i], b5, acc[i*6+5]);
                }
            }
            __syncthreads();
        }

        // epilogue: add qkv bias, write C tile [64x192]
        {
            float bq[6];
            #pragma unroll
            for (int j = 0; j < 6; j++) {
                int c = n0q + j;
                int gcol = (c >> 6) * 256 + p * 64 + (c & 63);
                bq[j] = qkv_b[gcol];
            }
            #pragma unroll
            for (int i = 0; i < 8; i++)
                #pragma unroll
                for (int j = 0; j < 6; j++)
                    s_c[(m0 + i) * PC + n0q + j] = acc[i * 6 + j] + bq[j];
        }
        __syncthreads();

        // l2-norm scales for q,k rows of these 4 heads
        {
            int hh = tid >> 6, m = tid & 63;
            const float* qp = s_c + m * PC + hh * 16;
            float sq = 0.f, sk = 0.f;
            #pragma unroll
            for (int d = 0; d < 16; d++) {
                sq += qp[d] * qp[d];
                sk += qp[64 + d] * qp[64 + d];
            }
            s_rq[tid] = 1.f / fmaxf(sqrtf(sq), 1e-12f);
            s_rk[tid] = 1.f / fmaxf(sqrtf(sk), 1e-12f);
        }
        __syncthreads();

        // attention for heads p*4 .. p*4+3
        #pragma unroll 1
        for (int hh = 0; hh < 4; hh++) {
            int h = p * 4 + hh;
            #pragma unroll
            for (int i = 0; i < 16; i++)
                s_bias[tid + i * 256] = g_bias[h * 4096 + tid + i * 256];
            __syncthreads();

            const float* qp = s_c + nrow * PC + hh * 16;
            float4 q0 = *(const float4*)(qp + 0);
            float4 q1 = *(const float4*)(qp + 4);
            float4 q2 = *(const float4*)(qp + 8);
            float4 q3 = *(const float4*)(qp + 12);
            float rqv = s_rq[hh * 64 + nrow];
            const float* srk = s_rk + hh * 64;

            float S[16];
            #pragma unroll
            for (int jj = 0; jj < 16; jj++) {
                int j = jj * 4 + dg;
                const float* kr = s_c + j * PC + 64 + hh * 16;
                float4 k0 = *(const float4*)(kr + 0);
                float4 k1 = *(const float4*)(kr + 4);
                float4 k2 = *(const float4*)(kr + 8);
                float4 k3 = *(const float4*)(kr + 12);
                float d0 = q0.x*k0.x + q0.y*k0.y + q0.z*k0.z + q0.w*k0.w;
                float d1 = q1.x*k1.x + q1.y*k1.y + q1.z*k1.z + q1.w*k1.w;
                float d2 = q2.x*k2.x + q2.y*k2.y + q2.z*k2.z + q2.w*k2.w;
                float d3 = q3.x*k3.x + q3.y*k3.y + q3.z*k3.z + q3.w*k3.w;
                S[jj] = (d0 + d1 + d2 + d3) * rqv * srk[j] + s_bias[nrow * 64 + j];
            }
            float mx = S[0];
            #pragma unroll
            for (int jj = 1; jj < 16; jj++) mx = fmaxf(mx, S[jj]);
            mx = fmaxf(mx, __shfl_xor_sync(0xffffffffu, mx, 1));
            mx = fmaxf(mx, __shfl_xor_sync(0xffffffffu, mx, 2));
            float sum = 0.f;
            #pragma unroll
            for (int jj = 0; jj < 16; jj++) { S[jj] = __expf(S[jj] - mx); sum += S[jj]; }
            sum += __shfl_xor_sync(0xffffffffu, sum, 1);
            sum += __shfl_xor_sync(0xffffffffu, sum, 2);

            float o[16];
            #pragma unroll
            for (int d = 0; d < 16; d++) o[d] = 0.f;
            #pragma unroll
            for (int jj = 0; jj < 16; jj++) {
                float pw = S[jj];
                const float* vr = s_c + (jj * 4 + dg) * PC + 128 + hh * 16;
                float4 v0 = *(const float4*)(vr + 0);
                float4 v1 = *(const float4*)(vr + 4);
                float4 v2 = *(const float4*)(vr + 8);
                float4 v3 = *(const float4*)(vr + 12);
                o[0]  = fmaf(pw, v0.x, o[0]);  o[1]  = fmaf(pw, v0.y, o[1]);
                o[2]  = fmaf(pw, v0.z, o[2]);  o[3]  = fmaf(pw, v0.w, o[3]);
                o[4]  = fmaf(pw, v1.x, o[4]);  o[5]  = fmaf(pw, v1.y, o[5]);
                o[6]  = fmaf(pw, v1.z, o[6]);  o[7]  = fmaf(pw, v1.w, o[7]);
                o[8]  = fmaf(pw, v2.x, o[8]);  o[9]  = fmaf(pw, v2.y, o[9]);
                o[10] = fmaf(pw, v2.z, o[10]); o[11] = fmaf(pw, v2.w, o[11]);
                o[12] = fmaf(pw, v3.x, o[12]); o[13] = fmaf(pw, v3.y, o[13]);
                o[14] = fmaf(pw, v3.z, o[14]); o[15] = fmaf(pw, v3.w, o[15]);
            }
            #pragma unroll
            for (int d = 0; d < 16; d++) {
                o[d] += __shfl_xor_sync(0xffffffffu, o[d], 1);
                o[d] += __shfl_xor_sync(0xffffffffu, o[d], 2);
            }
            if (dg == 0) {
                float rs = 1.f / sum;
                #pragma unroll
                for (int d = 0; d < 16; d++)
                    s_oT[(h * 16 + d) * PNT + nrow] = o[d] * rs;
            }
            __syncthreads();
        }
    }

    // ---------- phase 3: proj GEMM [64x256] = oT^T @ proj_w, write to s_t ----------
    {
        float acc[64];
        #pragma unroll
        for (int i = 0; i < 64; i++) acc[i] = 0.f;

        #pragma unroll
        for (int i = 0; i < 4; i++) {
            int idx = tid + i * 256;
            int row = idx >> 6;
            int c4  = (idx & 63) * 4;
            cp16(s_w2 + row * PW2 + c4, proj_w + row * 256 + c4);
        }
        cp_commit();

        #pragma unroll 1
        for (int blk = 0; blk < 16; blk++) {
            int bf = blk & 1;
            if (blk < 15) {
                int kb = (blk + 1) * 16;
                #pragma unroll
                for (int i = 0; i < 4; i++) {
                    int idx = tid + i * 256;
                    int row = idx >> 6;
                    int c4  = (idx & 63) * 4;
                    cp16(s_w2 + ((blk + 1) & 1) * 4160 + row * PW2 + c4,
                         proj_w + (kb + row) * 256 + c4);
                }
                cp_commit();
                cp_wait1();
            } else {
                cp_wait0();
            }
            __syncthreads();
            const float* Wb = s_w2 + bf * 4160;
            #pragma unroll
            for (int kk = 0; kk < 16; kk++) {
                const float* A = s_oT + (blk * 16 + kk) * PNT + m0;
                float4 a0 = *(const float4*)A;
                float4 a1 = *(const float4*)(A + 4);
                const float* Bp = Wb + kk * PW2 + n0p;
                float4 w0 = *(const float4*)Bp;
                float4 w1 = *(const float4*)(Bp + 4);
                float av[8] = {a0.x, a0.y, a0.z, a0.w, a1.x, a1.y, a1.z, a1.w};
                float bv[8] = {w0.x, w0.y, w0.z, w0.w, w1.x, w1.y, w1.z, w1.w};
                #pragma unroll
                for (int i = 0; i < 8; i++)
                    #pragma unroll
                    for (int j = 0; j < 8; j++)
                        acc[i * 8 + j] = fmaf(av[i], bv[j], acc[i * 8 + j]);
            }
            __syncthreads();
        }

        float pb[8];
        #pragma unroll
        for (int j = 0; j < 8; j++) pb[j] = proj_b[n0p + j];
        #pragma unroll
        for (int i = 0; i < 8; i++)
            #pragma unroll
            for (int j = 0; j < 8; j++)
                s_t[(m0 + i) * PT + n0p + j] = acc[i * 8 + j] + pb[j];
    }
    __syncthreads();

    // ---------- phase 4: residual t += x (coalesced global reload) ----------
    #pragma unroll 8
    for (int i = 0; i < 64; i++) {
        int idx = tid + i * 256;
        int ch  = idx >> 6;
        int n   = idx & 63;
        s_t[n * PT + ch] += Xb[ch * 65536 + (n >> 3) * 256 + (n & 7)];
    }
    __syncthreads();

    // ---------- phase 5a: post-LN stats ----------
    for (int n = warp; n < 64; n += 8) {
        float s = 0.f, s2 = 0.f;
        #pragma unroll
        for (int j = 0; j < 8; j++) {
            float v = s_t[n * PT + lane + 32 * j];
            s += v; s2 += v * v;
        }
        #pragma unroll
        for (int o = 16; o; o >>= 1) {
            s  += __shfl_xor_sync(0xffffffffu, s,  o);
            s2 += __shfl_xor_sync(0xffffffffu, s2, o);
        }
        float mean = s * (1.f / 256.f);
        if (lane == 0) {
            s_m[n] = mean;
            s_i[n] = rsqrtf(s2 * (1.f / 256.f) - mean * mean + 1e-5f);
        }
    }
    __syncthreads();

    // ---------- phase 5b: y = t + LN(t)*g + b, scatter out ----------
    #pragma unroll 8
    for (int i = 0; i < 64; i++) {
        int idx = tid + i * 256;
        int ch  = idx >> 6;
        int n   = idx & 63;
        float v = s_t[n * PT + ch];
        float y = v + (v - s_m[n]) * s_i[n] * post_g[ch] + post_b[ch];
        Ob[ch * 65536 + (n >> 3) * 256 + (n & 7)] = y;
    }
}

extern "C" void kernel_launch(void* const* d_in, const int* in_sizes, int n_in,
                              void* d_out, int out_size) {
    const float* X      = (const float*)d_in[0];
    const float* pre_g  = (const float*)d_in[1];
    const float* pre_b  = (const float*)d_in[2];
    const float* post_g = (const float*)d_in[3];
    const float* post_b = (const float*)d_in[4];
    const float* qkv_w  = (const float*)d_in[5];
    const float* qkv_b  = (const float*)d_in[6];
    const float* proj_w = (const float*)d_in[7];
    const float* proj_b = (const float*)d_in[8];
    const float* rtab   = (const float*)d_in[9];
    const int*   ridx   = (const int*)d_in[10];
    float* out = (float*)d_out;

    const int smem_bytes = SMEM_FLOATS * 4;
    cudaFuncSetAttribute(window_attn_kernel,
                         cudaFuncAttributeMaxDynamicSharedMemorySize, smem_bytes);

    bias_precompute<<<256, 256>>>(rtab, ridx);
    window_attn_kernel<<<2048, 256, smem_bytes>>>(
        X, pre_g, pre_b, post_g, post_b, qkv_w, qkv_b, proj_w, proj_b, out);
}

// round 6
// speedup vs baseline: 7.8252x; 1.7708x over previous
#include <cuda_runtime.h>
#include <cuda_bf16.h>
#include <cstdint>

#define HEADS 16
#define NW 64
#define CH 256
#define PC 196      // pitch s_c [64 x 192] fp32
#define PX 257      // pitch s_x [64 x 256] fp32
#define PA 264      // pitch bf16 activation buffers [64 x 256]
#define PWT 40      // pitch bf16 weight tiles [n x 32k]

// smem float offsets
#define OFF_X  0        // s_x  : 64*257 = 16448 fl (X window, later residual t)
#define OFF_C  16448    // s_c  : 64*196 = 12544 fl (qkv out / aliased proj W tiles)
#define OFF_AN 28992    // s_an : bf16 [64][264] = 8448 fl (LN out)
#define OFF_AB 37440    // s_ab : bf16 [64][264] = 8448 fl (attn out)
#define OFF_WQ 45888    // s_wq : bf16 2x(192*40) = 7680 fl (aliased s_bias 4096 fl)
#define OFF_RQ 53568
#define OFF_RK 53824
#define OFF_M  54080
#define OFF_I  54144
#define SMEM_FLOATS 54208

__device__ float g_bias[HEADS * NW * NW];
__device__ __nv_bfloat16 g_wq[4 * 8 * 192 * 32];   // [pass][kb][n(192)][k(32)]
__device__ __nv_bfloat16 g_wp[8 * 256 * 32];       // [kb][n(256)][k(32)]

__global__ void bias_precompute(const float* __restrict__ table,
                                const int* __restrict__ ridx) {
    int t = blockIdx.x * blockDim.x + threadIdx.x;
    if (t < HEADS * NW * NW) {
        int h = t >> 12;
        int ij = t & 4095;
        g_bias[t] = table[ridx[ij] * HEADS + h];
    }
}
__global__ void prep_wq(const float* __restrict__ qkv_w) {
    int t = blockIdx.x * blockDim.x + threadIdx.x;
    if (t >= 4 * 49152) return;
    int p = t / 49152, r = t % 49152;
    int kb = r / 6144, r2 = r % 6144;
    int n = r2 / 32, k = r2 % 32;
    int gcol = (n >> 6) * 256 + p * 64 + (n & 63);
    g_wq[t] = __float2bfloat16(qkv_w[(kb * 32 + k) * 768 + gcol]);
}
__global__ void prep_wp(const float* __restrict__ proj_w) {
    int t = blockIdx.x * blockDim.x + threadIdx.x;
    if (t >= 8 * 8192) return;
    int kb = t / 8192, r = t % 8192;
    int n = r / 32, k = r % 32;
    g_wp[t] = __float2bfloat16(proj_w[(kb * 32 + k) * 256 + n]);
}

__device__ __forceinline__ void cp16s(void* dst, const void* src) {
    uint32_t d = (uint32_t)__cvta_generic_to_shared(dst);
    asm volatile("cp.async.ca.shared.global [%0], [%1], 16;" :: "r"(d), "l"(src));
}
__device__ __forceinline__ void cp_commit() { asm volatile("cp.async.commit_group;"); }
__device__ __forceinline__ void cp_wait1()  { asm volatile("cp.async.wait_group 1;"); }
__device__ __forceinline__ void cp_wait0()  { asm volatile("cp.async.wait_group 0;"); }

__device__ __forceinline__ void mma16816(float* c, uint32_t a0, uint32_t a1,
                                         uint32_t a2, uint32_t a3,
                                         uint32_t b0, uint32_t b1) {
    asm volatile("mma.sync.aligned.m16n8k16.row.col.f32.bf16.bf16.f32 "
        "{%0,%1,%2,%3}, {%4,%5,%6,%7}, {%8,%9}, {%0,%1,%2,%3};"
        : "+f"(c[0]), "+f"(c[1]), "+f"(c[2]), "+f"(c[3])
        : "r"(a0), "r"(a1), "r"(a2), "r"(a3), "r"(b0), "r"(b1));
}

__global__ __launch_bounds__(256, 1)
void window_attn_kernel(const float* __restrict__ X,
                        const float* __restrict__ pre_g, const float* __restrict__ pre_b,
                        const float* __restrict__ post_g, const float* __restrict__ post_b,
                        const float* __restrict__ qkv_b, const float* __restrict__ proj_b,
                        float* __restrict__ out) {
    extern __shared__ float sm[];
    float*     s_x  = sm + OFF_X;
    float*     s_c  = sm + OFF_C;
    uint16_t*  s_an = (uint16_t*)(sm + OFF_AN);
    uint16_t*  s_ab = (uint16_t*)(sm + OFF_AB);
    uint16_t*  s_wq = (uint16_t*)(sm + OFF_WQ);
    uint16_t*  s_wp = (uint16_t*)(sm + OFF_C);    // alias after attention done
    float*     s_bias = sm + OFF_WQ;              // alias during attention
    float*     s_rq = sm + OFF_RQ;
    float*     s_rk = sm + OFF_RK;
    float*     s_m  = sm + OFF_M;
    float*     s_i  = sm + OFF_I;

    const int w    = blockIdx.x;
    const int b    = w >> 10;
    const int hi   = (w >> 5) & 31;
    const int wi   = w & 31;
    const int tid  = threadIdx.x;
    const int lane = tid & 31;
    const int warp = tid >> 5;

    const float* Xb = X + (size_t)b * (CH * 65536) + hi * 8 * 256 + wi * 8;
    float*       Ob = out + (size_t)b * (CH * 65536) + hi * 8 * 256 + wi * 8;

    // ---------- phase 0: load X window [m][c] fp32 ----------
    #pragma unroll 8
    for (int i = 0; i < 64; i++) {
        int idx = tid + i * 256;
        int ch  = idx >> 6;
        int n   = idx & 63;
        s_x[n * PX + ch] = Xb[ch * 65536 + (n >> 3) * 256 + (n & 7)];
    }
    __syncthreads();

    // ---------- phase 1: pre-LN -> s_an bf16 [m][c] ----------
    for (int m = warp; m < 64; m += 8) {
        float v[8];
        float s = 0.f, s2 = 0.f;
        #pragma unroll
        for (int j = 0; j < 8; j++) {
            v[j] = s_x[m * PX + lane + 32 * j];
            s += v[j]; s2 += v[j] * v[j];
        }
        #pragma unroll
        for (int o = 16; o; o >>= 1) {
            s  += __shfl_xor_sync(0xffffffffu, s,  o);
            s2 += __shfl_xor_sync(0xffffffffu, s2, o);
        }
        float mean = s * (1.f / 256.f);
        float inv  = rsqrtf(s2 * (1.f / 256.f) - mean * mean + 1e-5f);
        #pragma unroll
        for (int j = 0; j < 8; j++) {
            int c = lane + 32 * j;
            float y = (v[j] - mean) * inv * pre_g[c] + pre_b[c];
            __nv_bfloat16 h = __float2bfloat16(y);
            s_an[m * PA + c] = *(uint16_t*)&h;
        }
    }
    __syncthreads();

    // mma thread mapping
    const int g   = lane >> 2;          // 0..7
    const int tq  = (lane & 3) * 2;     // 0,2,4,6
    const int m0  = (warp & 3) * 16;    // m-tile
    const int nh  = warp >> 2;          // n-half
    const int nrow = tid >> 2;          // attention row
    const int dg   = tid & 3;           // attention col group

    // ---------- phase 2: 4 passes of (qkv HMMA GEMM for 4 heads -> attention) ----------
    #pragma unroll 1
    for (int p = 0; p < 4; p++) {
        float acc[48];
        #pragma unroll
        for (int i = 0; i < 48; i++) acc[i] = 0.f;

        const __nv_bfloat16* gw = g_wq + p * 49152;
        // prologue: kb=0 tile
        #pragma unroll
        for (int i = 0; i < 3; i++) {
            int idx = tid + i * 256;
            int n = idx >> 2, kc = (idx & 3) * 8;
            cp16s(s_wq + n * PWT + kc, gw + n * 32 + kc);
        }
        cp_commit();

        #pragma unroll 1
        for (int kb = 0; kb < 8; kb++) {
            if (kb < 7) {
                const __nv_bfloat16* gwn = gw + (kb + 1) * 6144;
                uint16_t* dstb = s_wq + ((kb + 1) & 1) * 7680;
                #pragma unroll
                for (int i = 0; i < 3; i++) {
                    int idx = tid + i * 256;
                    int n = idx >> 2, kc = (idx & 3) * 8;
                    cp16s(dstb + n * PWT + kc, gwn + n * 32 + kc);
                }
                cp_commit();
                cp_wait1();
            } else {
                cp_wait0();
            }
            __syncthreads();
            const uint16_t* Wb = s_wq + (kb & 1) * 7680;
            #pragma unroll
            for (int ks = 0; ks < 2; ks++) {
                const uint16_t* Ap = s_an + (m0 + g) * PA + kb * 32 + ks * 16 + tq;
                uint32_t a0 = *(const uint32_t*)Ap;
                uint32_t a1 = *(const uint32_t*)(Ap + 8 * PA);
                uint32_t a2 = *(const uint32_t*)(Ap + 8);
                uint32_t a3 = *(const uint32_t*)(Ap + 8 * PA + 8);
                const uint16_t* Bp = Wb + ks * 16 + tq;
                #pragma unroll
                for (int j = 0; j < 12; j++) {
                    int n = nh * 96 + j * 8 + g;
                    uint32_t b0 = *(const uint32_t*)(Bp + n * PWT);
                    uint32_t b1 = *(const uint32_t*)(Bp + n * PWT + 8);
                    mma16816(&acc[j * 4], a0, a1, a2, a3, b0, b1);
                }
            }
            __syncthreads();
        }

        // epilogue: + bias -> s_c fp32 [64 x 192]
        #pragma unroll
        for (int j = 0; j < 12; j++) {
            int n = nh * 96 + j * 8 + tq;
            int gc = (n >> 6) * 256 + p * 64 + (n & 63);
            float bq0 = qkv_b[gc], bq1 = qkv_b[gc + 1];
            s_c[(m0 + g) * PC + n]         = acc[j * 4 + 0] + bq0;
            s_c[(m0 + g) * PC + n + 1]     = acc[j * 4 + 1] + bq1;
            s_c[(m0 + g + 8) * PC + n]     = acc[j * 4 + 2] + bq0;
            s_c[(m0 + g + 8) * PC + n + 1] = acc[j * 4 + 3] + bq1;
        }
        __syncthreads();

        // l2-norm scales for q,k rows of these 4 heads
        {
            int hh = tid >> 6, m = tid & 63;
            const float* qp = s_c + m * PC + hh * 16;
            float sq = 0.f, sk = 0.f;
            #pragma unroll
            for (int d = 0; d < 16; d++) {
                sq += qp[d] * qp[d];
                sk += qp[64 + d] * qp[64 + d];
            }
            s_rq[tid] = 1.f / fmaxf(sqrtf(sq), 1e-12f);
            s_rk[tid] = 1.f / fmaxf(sqrtf(sk), 1e-12f);
        }
        __syncthreads();

        // attention for heads p*4 .. p*4+3 (fp32, unchanged from R2)
        #pragma unroll 1
        for (int hh = 0; hh < 4; hh++) {
            int h = p * 4 + hh;
            #pragma unroll
            for (int i = 0; i < 16; i++)
                s_bias[tid + i * 256] = g_bias[h * 4096 + tid + i * 256];
            __syncthreads();

            const float* qp = s_c + nrow * PC + hh * 16;
            float4 q0 = *(const float4*)(qp + 0);
            float4 q1 = *(const float4*)(qp + 4);
            float4 q2 = *(const float4*)(qp + 8);
            float4 q3 = *(const float4*)(qp + 12);
            float rqv = s_rq[hh * 64 + nrow];
            const float* srk = s_rk + hh * 64;

            float S[16];
            #pragma unroll
            for (int jj = 0; jj < 16; jj++) {
                int j = jj * 4 + dg;
                const float* kr = s_c + j * PC + 64 + hh * 16;
                float4 k0 = *(const float4*)(kr + 0);
                float4 k1 = *(const float4*)(kr + 4);
                float4 k2 = *(const float4*)(kr + 8);
                float4 k3 = *(const float4*)(kr + 12);
                float d0 = q0.x*k0.x + q0.y*k0.y + q0.z*k0.z + q0.w*k0.w;
                float d1 = q1.x*k1.x + q1.y*k1.y + q1.z*k1.z + q1.w*k1.w;
                float d2 = q2.x*k2.x + q2.y*k2.y + q2.z*k2.z + q2.w*k2.w;
                float d3 = q3.x*k3.x + q3.y*k3.y + q3.z*k3.z + q3.w*k3.w;
                S[jj] = (d0 + d1 + d2 + d3) * rqv * srk[j] + s_bias[nrow * 64 + j];
            }
            float mx = S[0];
            #pragma unroll
            for (int jj = 1; jj < 16; jj++) mx = fmaxf(mx, S[jj]);
            mx = fmaxf(mx, __shfl_xor_sync(0xffffffffu, mx, 1));
            mx = fmaxf(mx, __shfl_xor_sync(0xffffffffu, mx, 2));
            float sum = 0.f;
            #pragma unroll
            for (int jj = 0; jj < 16; jj++) { S[jj] = __expf(S[jj] - mx); sum += S[jj]; }
            sum += __shfl_xor_sync(0xffffffffu, sum, 1);
            sum += __shfl_xor_sync(0xffffffffu, sum, 2);

            float o[16];
            #pragma unroll
            for (int d = 0; d < 16; d++) o[d] = 0.f;
            #pragma unroll
            for (int jj = 0; jj < 16; jj++) {
                float pw = S[jj];
                const float* vr = s_c + (jj * 4 + dg) * PC + 128 + hh * 16;
                float4 v0 = *(const float4*)(vr + 0);
                float4 v1 = *(const float4*)(vr + 4);
                float4 v2 = *(const float4*)(vr + 8);
                float4 v3 = *(const float4*)(vr + 12);
                o[0]  = fmaf(pw, v0.x, o[0]);  o[1]  = fmaf(pw, v0.y, o[1]);
                o[2]  = fmaf(pw, v0.z, o[2]);  o[3]  = fmaf(pw, v0.w, o[3]);
                o[4]  = fmaf(pw, v1.x, o[4]);  o[5]  = fmaf(pw, v1.y, o[5]);
                o[6]  = fmaf(pw, v1.z, o[6]);  o[7]  = fmaf(pw, v1.w, o[7]);
                o[8]  = fmaf(pw, v2.x, o[8]);  o[9]  = fmaf(pw, v2.y, o[9]);
                o[10] = fmaf(pw, v2.z, o[10]); o[11] = fmaf(pw, v2.w, o[11]);
                o[12] = fmaf(pw, v3.x, o[12]); o[13] = fmaf(pw, v3.y, o[13]);
                o[14] = fmaf(pw, v3.z, o[14]); o[15] = fmaf(pw, v3.w, o[15]);
            }
            #pragma unroll
            for (int d = 0; d < 16; d++) {
                o[d] += __shfl_xor_sync(0xffffffffu, o[d], 1);
                o[d] += __shfl_xor_sync(0xffffffffu, o[d], 2);
            }
            if (dg == 0) {
                float rs = 1.f / sum;
                uint32_t* op = (uint32_t*)(s_ab + nrow * PA + h * 16);
                #pragma unroll
                for (int d2 = 0; d2 < 8; d2++) {
                    __nv_bfloat162 pr = __floats2bfloat162_rn(o[2 * d2] * rs, o[2 * d2 + 1] * rs);
                    op[d2] = *(uint32_t*)&pr;
                }
            }
            __syncthreads();
        }
    }

    // ---------- phase 3: proj HMMA GEMM, epilogue adds residual into s_x ----------
    {
        float acc[64];
        #pragma unroll
        for (int i = 0; i < 64; i++) acc[i] = 0.f;

        #pragma unroll
        for (int i = 0; i < 4; i++) {
            int idx = tid + i * 256;
            int n = idx >> 2, kc = (idx & 3) * 8;
            cp16s(s_wp + n * PWT + kc, g_wp + n * 32 + kc);
        }
        cp_commit();

        #pragma unroll 1
        for (int kb = 0; kb < 8; kb++) {
            if (kb < 7) {
                const __nv_bfloat16* gwn = g_wp + (kb + 1) * 8192;
                uint16_t* dstb = s_wp + ((kb + 1) & 1) * 10240;
                #pragma unroll
                for (int i = 0; i < 4; i++) {
                    int idx = tid + i * 256;
                    int n = idx >> 2, kc = (idx & 3) * 8;
                    cp16s(dstb + n * PWT + kc, gwn + n * 32 + kc);
                }
                cp_commit();
                cp_wait1();
            } else {
                cp_wait0();
            }
            __syncthreads();
            const uint16_t* Wb = s_wp + (kb & 1) * 10240;
            #pragma unroll
            for (int ks = 0; ks < 2; ks++) {
                const uint16_t* Ap = s_ab + (m0 + g) * PA + kb * 32 + ks * 16 + tq;
                uint32_t a0 = *(const uint32_t*)Ap;
                uint32_t a1 = *(const uint32_t*)(Ap + 8 * PA);
                uint32_t a2 = *(const uint32_t*)(Ap + 8);
                uint32_t a3 = *(const uint32_t*)(Ap + 8 * PA + 8);
                const uint16_t* Bp = Wb + ks * 16 + tq;
                #pragma unroll
                for (int j = 0; j < 16; j++) {
                    int n = nh * 128 + j * 8 + g;
                    uint32_t b0 = *(const uint32_t*)(Bp + n * PWT);
                    uint32_t b1 = *(const uint32_t*)(Bp + n * PWT + 8);
                    mma16816(&acc[j * 4], a0, a1, a2, a3, b0, b1);
                }
            }
            __syncthreads();
        }

        #pragma unroll
        for (int j = 0; j < 16; j++) {
            int n = nh * 128 + j * 8 + tq;
            float pb0 = proj_b[n], pb1 = proj_b[n + 1];
            s_x[(m0 + g) * PX + n]         += acc[j * 4 + 0] + pb0;
            s_x[(m0 + g) * PX + n + 1]     += acc[j * 4 + 1] + pb1;
            s_x[(m0 + g + 8) * PX + n]     += acc[j * 4 + 2] + pb0;
            s_x[(m0 + g + 8) * PX + n + 1] += acc[j * 4 + 3] + pb1;
        }
    }
    __syncthreads();

    // ---------- phase 4a: post-LN stats on t (= s_x) ----------
    for (int n = warp; n < 64; n += 8) {
        float s = 0.f, s2 = 0.f;
        #pragma unroll
        for (int j = 0; j < 8; j++) {
            float v = s_x[n * PX + lane + 32 * j];
            s += v; s2 += v * v;
        }
        #pragma unroll
        for (int o = 16; o; o >>= 1) {
            s  += __shfl_xor_sync(0xffffffffu, s,  o);
            s2 += __shfl_xor_sync(0xffffffffu, s2, o);
        }
        float mean = s * (1.f / 256.f);
        if (lane == 0) {
            s_m[n] = mean;
            s_i[n] = rsqrtf(s2 * (1.f / 256.f) - mean * mean + 1e-5f);
        }
    }
    __syncthreads();

    // ---------- phase 4b: y = t + LN(t)*g + b, scatter out ----------
    #pragma unroll 8
    for (int i = 0; i < 64; i++) {
        int idx = tid + i * 256;
        int ch  = idx >> 6;
        int n   = idx & 63;
        float v = s_x[n * PX + ch];
        float y = v + (v - s_m[n]) * s_i[n] * post_g[ch] + post_b[ch];
        Ob[ch * 65536 + (n >> 3) * 256 + (n & 7)] = y;
    }
}

extern "C" void kernel_launch(void* const* d_in, const int* in_sizes, int n_in,
                              void* d_out, int out_size) {
    const float* X      = (const float*)d_in[0];
    const float* pre_g  = (const float*)d_in[1];
    const float* pre_b  = (const float*)d_in[2];
    const float* post_g = (const float*)d_in[3];
    const float* post_b = (const float*)d_in[4];
    const float* qkv_w  = (const float*)d_in[5];
    const float* qkv_b  = (const float*)d_in[6];
    const float* proj_w = (const float*)d_in[7];
    const float* proj_b = (const float*)d_in[8];
    const float* rtab   = (const float*)d_in[9];
    const int*   ridx   = (const int*)d_in[10];
    float* out = (float*)d_out;

    const int smem_bytes = SMEM_FLOATS * 4;
    cudaFuncSetAttribute(window_attn_kernel,
                         cudaFuncAttributeMaxDynamicSharedMemorySize, smem_bytes);

    bias_precompute<<<256, 256>>>(rtab, ridx);
    prep_wq<<<768, 256>>>(qkv_w);
    prep_wp<<<256, 256>>>(proj_w);
    window_attn_kernel<<<2048, 256, smem_bytes>>>(
        X, pre_g, pre_b, post_g, post_b, qkv_b, proj_b, out);
}

// round 7
// speedup vs baseline: 14.4749x; 1.8498x over previous
#include <cuda_runtime.h>
#include <cuda_bf16.h>
#include <cstdint>

#define HEADS 16
#define NW 64
#define CH 256
#define PC 196      // pitch s_c [64 x 192] fp32
#define PX 257      // pitch s_x [64 x 256] fp32
#define PA 264      // pitch bf16 activation buffers [64 x 256] (halves)
#define PWT 40      // pitch bf16 weight tiles [n x 32k] (halves)
#define PQK 20      // pitch bf16 q/k head tiles [64 x 16] (halves)
#define PVT 72      // pitch bf16 vT head tiles [16 x 64] (halves)
#define PB 72       // pitch bf16 bias tiles [64 x 64] (halves)

// smem float offsets
#define OFF_X  0        // s_x : 64*257 = 16448 fl (X window / residual t)
#define OFF_C  16448    // s_c : 64*196 fp32 (qkv out) | bias bf16 [4][64][72] | proj W tiles
#define OFF_AN 28992    // s_an: bf16 [64][264] (LN out)
#define OFF_AB 37440    // s_ab: bf16 [64][264] (attn out)
#define OFF_W  45888    // s_wq: bf16 2x(192*40) | q/k/vT bf16 head tiles
#define OFF_RQ 53568
#define OFF_RK 53824
#define OFF_M  54080
#define OFF_I  54144
#define SMEM_FLOATS 54208

__device__ __nv_bfloat16 g_biasb[HEADS * NW * NW];
__device__ __nv_bfloat16 g_wq[4 * 8 * 192 * 32];   // [pass][kb][n(192)][k(32)]
__device__ __nv_bfloat16 g_wp[8 * 256 * 32];       // [kb][n(256)][k(32)]

__global__ void prep_bias(const float* __restrict__ table,
                          const int* __restrict__ ridx) {
    int t = blockIdx.x * blockDim.x + threadIdx.x;
    if (t < HEADS * NW * NW) {
        int h = t >> 12;
        int ij = t & 4095;
        g_biasb[t] = __float2bfloat16(table[ridx[ij] * HEADS + h]);
    }
}
__global__ void prep_wq(const float* __restrict__ qkv_w) {
    int t = blockIdx.x * blockDim.x + threadIdx.x;
    if (t >= 4 * 49152) return;
    int p = t / 49152, r = t % 49152;
    int kb = r / 6144, r2 = r % 6144;
    int n = r2 / 32, k = r2 % 32;
    int gcol = (n >> 6) * 256 + p * 64 + (n & 63);
    g_wq[t] = __float2bfloat16(qkv_w[(kb * 32 + k) * 768 + gcol]);
}
__global__ void prep_wp(const float* __restrict__ proj_w) {
    int t = blockIdx.x * blockDim.x + threadIdx.x;
    if (t >= 8 * 8192) return;
    int kb = t / 8192, r = t % 8192;
    int n = r / 32, k = r % 32;
    g_wp[t] = __float2bfloat16(proj_w[(kb * 32 + k) * 256 + n]);
}

__device__ __forceinline__ void cp16s(void* dst, const void* src) {
    uint32_t d = (uint32_t)__cvta_generic_to_shared(dst);
    asm volatile("cp.async.ca.shared.global [%0], [%1], 16;" :: "r"(d), "l"(src));
}
__device__ __forceinline__ void cp_commit() { asm volatile("cp.async.commit_group;"); }
__device__ __forceinline__ void cp_wait1()  { asm volatile("cp.async.wait_group 1;"); }
__device__ __forceinline__ void cp_wait0()  { asm volatile("cp.async.wait_group 0;"); }

__device__ __forceinline__ void mma16816(float* c, uint32_t a0, uint32_t a1,
                                         uint32_t a2, uint32_t a3,
                                         uint32_t b0, uint32_t b1) {
    asm volatile("mma.sync.aligned.m16n8k16.row.col.f32.bf16.bf16.f32 "
        "{%0,%1,%2,%3}, {%4,%5,%6,%7}, {%8,%9}, {%0,%1,%2,%3};"
        : "+f"(c[0]), "+f"(c[1]), "+f"(c[2]), "+f"(c[3])
        : "r"(a0), "r"(a1), "r"(a2), "r"(a3), "r"(b0), "r"(b1));
}
__device__ __forceinline__ uint32_t pack2(float lo, float hi) {
    __nv_bfloat162 h = __floats2bfloat162_rn(lo, hi);
    return *(uint32_t*)&h;
}
__device__ __forceinline__ float2 unpack2(uint32_t u) {
    __nv_bfloat162 h = *(__nv_bfloat162*)&u;
    return make_float2(__bfloat162float(h.x), __bfloat162float(h.y));
}

__global__ __launch_bounds__(256, 1)
void window_attn_kernel(const float* __restrict__ X,
                        const float* __restrict__ pre_g, const float* __restrict__ pre_b,
                        const float* __restrict__ post_g, const float* __restrict__ post_b,
                        const float* __restrict__ qkv_b, const float* __restrict__ proj_b,
                        float* __restrict__ out) {
    extern __shared__ float sm[];
    float*     s_x  = sm + OFF_X;
    float*     s_c  = sm + OFF_C;
    uint16_t*  s_an = (uint16_t*)(sm + OFF_AN);
    uint16_t*  s_ab = (uint16_t*)(sm + OFF_AB);
    uint16_t*  s_wq = (uint16_t*)(sm + OFF_W);
    uint16_t*  s_wp = (uint16_t*)(sm + OFF_C);    // alias (after all attention)
    uint16_t*  s_bh = (uint16_t*)(sm + OFF_C);    // bias bf16, alias over s_c
    uint16_t*  s_qb = (uint16_t*)(sm + OFF_W);            // [4][64][20]
    uint16_t*  s_kb = s_qb + 4 * 64 * PQK;                // [4][64][20]
    uint16_t*  s_vb = s_kb + 4 * 64 * PQK;                // [4][16][72]
    float*     s_rq = sm + OFF_RQ;
    float*     s_rk = sm + OFF_RK;
    float*     s_m  = sm + OFF_M;
    float*     s_i  = sm + OFF_I;

    const int w    = blockIdx.x;
    const int b    = w >> 10;
    const int hi   = (w >> 5) & 31;
    const int wi   = w & 31;
    const int tid  = threadIdx.x;
    const int lane = tid & 31;
    const int warp = tid >> 5;

    const float* Xb = X + (size_t)b * (CH * 65536) + hi * 8 * 256 + wi * 8;
    float*       Ob = out + (size_t)b * (CH * 65536) + hi * 8 * 256 + wi * 8;

    // ---------- phase 0: load X window [m][c] fp32 ----------
    #pragma unroll 8
    for (int i = 0; i < 64; i++) {
        int idx = tid + i * 256;
        int ch  = idx >> 6;
        int n   = idx & 63;
        s_x[n * PX + ch] = Xb[ch * 65536 + (n >> 3) * 256 + (n & 7)];
    }
    __syncthreads();

    // ---------- phase 1: pre-LN -> s_an bf16 [m][c] ----------
    for (int m = warp; m < 64; m += 8) {
        float v[8];
        float s = 0.f, s2 = 0.f;
        #pragma unroll
        for (int j = 0; j < 8; j++) {
            v[j] = s_x[m * PX + lane + 32 * j];
            s += v[j]; s2 += v[j] * v[j];
        }
        #pragma unroll
        for (int o = 16; o; o >>= 1) {
            s  += __shfl_xor_sync(0xffffffffu, s,  o);
            s2 += __shfl_xor_sync(0xffffffffu, s2, o);
        }
        float mean = s * (1.f / 256.f);
        float inv  = rsqrtf(s2 * (1.f / 256.f) - mean * mean + 1e-5f);
        #pragma unroll
        for (int j = 0; j < 8; j++) {
            int c = lane + 32 * j;
            float y = (v[j] - mean) * inv * pre_g[c] + pre_b[c];
            __nv_bfloat16 h = __float2bfloat16(y);
            s_an[m * PA + c] = *(uint16_t*)&h;
        }
    }
    __syncthreads();

    // mma thread mapping
    const int g   = lane >> 2;          // 0..7
    const int tq  = (lane & 3) * 2;     // 0,2,4,6
    const int m0  = (warp & 3) * 16;    // GEMM m-tile
    const int nh  = warp >> 2;          // GEMM n-half

    // ---------- phase 2: 4 passes of (qkv HMMA -> convert -> HMMA attention) ----------
    #pragma unroll 1
    for (int p = 0; p < 4; p++) {
        float acc[48];
        #pragma unroll
        for (int i = 0; i < 48; i++) acc[i] = 0.f;

        const __nv_bfloat16* gw = g_wq + p * 49152;
        #pragma unroll
        for (int i = 0; i < 3; i++) {
            int idx = tid + i * 256;
            int n = idx >> 2, kc = (idx & 3) * 8;
            cp16s(s_wq + n * PWT + kc, gw + n * 32 + kc);
        }
        cp_commit();

        #pragma unroll 1
        for (int kb = 0; kb < 8; kb++) {
            if (kb < 7) {
                const __nv_bfloat16* gwn = gw + (kb + 1) * 6144;
                uint16_t* dstb = s_wq + ((kb + 1) & 1) * 7680;
                #pragma unroll
                for (int i = 0; i < 3; i++) {
                    int idx = tid + i * 256;
                    int n = idx >> 2, kc = (idx & 3) * 8;
                    cp16s(dstb + n * PWT + kc, gwn + n * 32 + kc);
                }
                cp_commit();
                cp_wait1();
            } else {
                cp_wait0();
            }
            __syncthreads();
            const uint16_t* Wb = s_wq + (kb & 1) * 7680;
            #pragma unroll
            for (int ks = 0; ks < 2; ks++) {
                const uint16_t* Ap = s_an + (m0 + g) * PA + kb * 32 + ks * 16 + tq;
                uint32_t a0 = *(const uint32_t*)Ap;
                uint32_t a1 = *(const uint32_t*)(Ap + 8 * PA);
                uint32_t a2 = *(const uint32_t*)(Ap + 8);
                uint32_t a3 = *(const uint32_t*)(Ap + 8 * PA + 8);
                const uint16_t* Bp = Wb + ks * 16 + tq;
                #pragma unroll
                for (int j = 0; j < 12; j++) {
                    int n = nh * 96 + j * 8 + g;
                    uint32_t b0 = *(const uint32_t*)(Bp + n * PWT);
                    uint32_t b1 = *(const uint32_t*)(Bp + n * PWT + 8);
                    mma16816(&acc[j * 4], a0, a1, a2, a3, b0, b1);
                }
            }
            __syncthreads();
        }

        // epilogue: + bias -> s_c fp32 [64 x 192]
        #pragma unroll
        for (int j = 0; j < 12; j++) {
            int n = nh * 96 + j * 8 + tq;
            int gc = (n >> 6) * 256 + p * 64 + (n & 63);
            float bq0 = qkv_b[gc], bq1 = qkv_b[gc + 1];
            s_c[(m0 + g) * PC + n]         = acc[j * 4 + 0] + bq0;
            s_c[(m0 + g) * PC + n + 1]     = acc[j * 4 + 1] + bq1;
            s_c[(m0 + g + 8) * PC + n]     = acc[j * 4 + 2] + bq0;
            s_c[(m0 + g + 8) * PC + n + 1] = acc[j * 4 + 3] + bq1;
        }
        __syncthreads();

        // l2-norm scales for q,k rows of these 4 heads
        {
            int hh = tid >> 6, m = tid & 63;
            const float* qp = s_c + m * PC + hh * 16;
            float sq = 0.f, sk = 0.f;
            #pragma unroll
            for (int d = 0; d < 16; d++) {
                sq += qp[d] * qp[d];
                sk += qp[64 + d] * qp[64 + d];
            }
            s_rq[tid] = 1.f / fmaxf(sqrtf(sq), 1e-12f);
            s_rk[tid] = 1.f / fmaxf(sqrtf(sk), 1e-12f);
        }
        __syncthreads();

        // convert: s_c fp32 -> bf16 q(hat)/k(hat)/vT head tiles (scales baked in)
        {
            int m = tid >> 2, qd = tid & 3;
            #pragma unroll
            for (int hh = 0; hh < 4; hh++) {
                float rqv = s_rq[hh * 64 + m];
                float rkv = s_rk[hh * 64 + m];
                float4 q4 = *(const float4*)(s_c + m * PC + hh * 16 + qd * 4);
                float4 k4 = *(const float4*)(s_c + m * PC + 64 + hh * 16 + qd * 4);
                float4 v4 = *(const float4*)(s_c + m * PC + 128 + hh * 16 + qd * 4);
                uint16_t* qp = s_qb + (hh * 64 + m) * PQK + qd * 4;
                uint16_t* kp = s_kb + (hh * 64 + m) * PQK + qd * 4;
                *(uint32_t*)(qp)     = pack2(q4.x * rqv, q4.y * rqv);
                *(uint32_t*)(qp + 2) = pack2(q4.z * rqv, q4.w * rqv);
                *(uint32_t*)(kp)     = pack2(k4.x * rkv, k4.y * rkv);
                *(uint32_t*)(kp + 2) = pack2(k4.z * rkv, k4.w * rkv);
                uint16_t* vp = s_vb + hh * 16 * PVT + (qd * 4) * PVT + m;
                __nv_bfloat16 h0 = __float2bfloat16(v4.x); vp[0]       = *(uint16_t*)&h0;
                __nv_bfloat16 h1 = __float2bfloat16(v4.y); vp[PVT]     = *(uint16_t*)&h1;
                __nv_bfloat16 h2 = __float2bfloat16(v4.z); vp[2 * PVT] = *(uint16_t*)&h2;
                __nv_bfloat16 h3 = __float2bfloat16(v4.w); vp[3 * PVT] = *(uint16_t*)&h3;
            }
        }
        __syncthreads();   // s_c fully consumed; tiles visible

        // bias bf16 -> smem (aliases s_c region), pitch 72
        #pragma unroll
        for (int i = 0; i < 8; i++) {
            int idx = tid + i * 256;
            int hh = idx >> 9, row = (idx >> 3) & 63, ck = idx & 7;
            cp16s(s_bh + (hh * 64 + row) * PB + ck * 8,
                  g_biasb + (p * 4 + hh) * 4096 + row * 64 + ck * 8);
        }
        cp_commit();
        cp_wait0();
        __syncthreads();

        // ---- HMMA attention: warp -> (head wh, row-half mh) ----
        {
            const int wh = warp >> 1, mh = warp & 1;
            const uint16_t* qh = s_qb + wh * 64 * PQK;
            const uint16_t* kh = s_kb + wh * 64 * PQK;
            const uint16_t* vh = s_vb + wh * 16 * PVT;
            const uint16_t* bh = s_bh + wh * 64 * PB;

            uint32_t qa[2][4];
            #pragma unroll
            for (int t = 0; t < 2; t++) {
                int r = mh * 32 + t * 16;
                qa[t][0] = *(const uint32_t*)(qh + (r + g) * PQK + tq);
                qa[t][1] = *(const uint32_t*)(qh + (r + g + 8) * PQK + tq);
                qa[t][2] = *(const uint32_t*)(qh + (r + g) * PQK + tq + 8);
                qa[t][3] = *(const uint32_t*)(qh + (r + g + 8) * PQK + tq + 8);
            }
            uint32_t kb0[8], kb1[8];
            #pragma unroll
            for (int j = 0; j < 8; j++) {
                kb0[j] = *(const uint32_t*)(kh + (j * 8 + g) * PQK + tq);
                kb1[j] = *(const uint32_t*)(kh + (j * 8 + g) * PQK + tq + 8);
            }

            float Sc[2][8][4];
            #pragma unroll
            for (int t = 0; t < 2; t++) {
                int r = mh * 32 + t * 16;
                #pragma unroll
                for (int j = 0; j < 8; j++) {
                    float2 f0 = unpack2(*(const uint32_t*)(bh + (r + g) * PB + j * 8 + tq));
                    float2 f1 = unpack2(*(const uint32_t*)(bh + (r + g + 8) * PB + j * 8 + tq));
                    Sc[t][j][0] = f0.x; Sc[t][j][1] = f0.y;
                    Sc[t][j][2] = f1.x; Sc[t][j][3] = f1.y;
                }
            }
            #pragma unroll
            for (int t = 0; t < 2; t++)
                #pragma unroll
                for (int j = 0; j < 8; j++)
                    mma16816(Sc[t][j], qa[t][0], qa[t][1], qa[t][2], qa[t][3],
                             kb0[j], kb1[j]);

            // softmax (no max subtraction: |logits| <= ~1.2)
            float inv0[2], inv1[2];
            #pragma unroll
            for (int t = 0; t < 2; t++) {
                float su0 = 0.f, su1 = 0.f;
                #pragma unroll
                for (int j = 0; j < 8; j++) {
                    Sc[t][j][0] = __expf(Sc[t][j][0]);
                    Sc[t][j][1] = __expf(Sc[t][j][1]);
                    Sc[t][j][2] = __expf(Sc[t][j][2]);
                    Sc[t][j][3] = __expf(Sc[t][j][3]);
                    su0 += Sc[t][j][0] + Sc[t][j][1];
                    su1 += Sc[t][j][2] + Sc[t][j][3];
                }
                su0 += __shfl_xor_sync(0xffffffffu, su0, 1);
                su0 += __shfl_xor_sync(0xffffffffu, su0, 2);
                su1 += __shfl_xor_sync(0xffffffffu, su1, 1);
                su1 += __shfl_xor_sync(0xffffffffu, su1, 2);
                inv0[t] = 1.f / su0;
                inv1[t] = 1.f / su1;
            }

            // PV: P fragments direct from registers
            float Oc[2][2][4];
            #pragma unroll
            for (int t = 0; t < 2; t++)
                #pragma unroll
                for (int nt = 0; nt < 2; nt++)
                    #pragma unroll
                    for (int i = 0; i < 4; i++) Oc[t][nt][i] = 0.f;

            #pragma unroll
            for (int ks = 0; ks < 4; ks++) {
                uint32_t vb0[2], vb1[2];
                #pragma unroll
                for (int nt = 0; nt < 2; nt++) {
                    vb0[nt] = *(const uint32_t*)(vh + (nt * 8 + g) * PVT + ks * 16 + tq);
                    vb1[nt] = *(const uint32_t*)(vh + (nt * 8 + g) * PVT + ks * 16 + tq + 8);
                }
                #pragma unroll
                for (int t = 0; t < 2; t++) {
                    uint32_t pa0 = pack2(Sc[t][2 * ks][0] * inv0[t],     Sc[t][2 * ks][1] * inv0[t]);
                    uint32_t pa1 = pack2(Sc[t][2 * ks][2] * inv1[t],     Sc[t][2 * ks][3] * inv1[t]);
                    uint32_t pa2 = pack2(Sc[t][2 * ks + 1][0] * inv0[t], Sc[t][2 * ks + 1][1] * inv0[t]);
                    uint32_t pa3 = pack2(Sc[t][2 * ks + 1][2] * inv1[t], Sc[t][2 * ks + 1][3] * inv1[t]);
                    #pragma unroll
                    for (int nt = 0; nt < 2; nt++)
                        mma16816(Oc[t][nt], pa0, pa1, pa2, pa3, vb0[nt], vb1[nt]);
                }
            }

            // write attn out bf16 to s_ab
            int hc = (p * 4 + wh) * 16;
            #pragma unroll
            for (int t = 0; t < 2; t++) {
                int r = mh * 32 + t * 16;
                #pragma unroll
                for (int nt = 0; nt < 2; nt++) {
                    *(uint32_t*)(s_ab + (r + g) * PA + hc + nt * 8 + tq) =
                        pack2(Oc[t][nt][0], Oc[t][nt][1]);
                    *(uint32_t*)(s_ab + (r + g + 8) * PA + hc + nt * 8 + tq) =
                        pack2(Oc[t][nt][2], Oc[t][nt][3]);
                }
            }
        }
        __syncthreads();   // q/k/vT + bias regions free for next pass
    }

    // ---------- phase 3: proj HMMA GEMM, epilogue adds residual into s_x ----------
    {
        float acc[64];
        #pragma unroll
        for (int i = 0; i < 64; i++) acc[i] = 0.f;

        #pragma unroll
        for (int i = 0; i < 4; i++) {
            int idx = tid + i * 256;
            int n = idx >> 2, kc = (idx & 3) * 8;
            cp16s(s_wp + n * PWT + kc, g_wp + n * 32 + kc);
        }
        cp_commit();

        #pragma unroll 1
        for (int kb = 0; kb < 8; kb++) {
            if (kb < 7) {
                const __nv_bfloat16* gwn = g_wp + (kb + 1) * 8192;
                uint16_t* dstb = s_wp + ((kb + 1) & 1) * 10240;
                #pragma unroll
                for (int i = 0; i < 4; i++) {
                    int idx = tid + i * 256;
                    int n = idx >> 2, kc = (idx & 3) * 8;
                    cp16s(dstb + n * PWT + kc, gwn + n * 32 + kc);
                }
                cp_commit();
                cp_wait1();
            } else {
                cp_wait0();
            }
            __syncthreads();
            const uint16_t* Wb = s_wp + (kb & 1) * 10240;
            #pragma unroll
            for (int ks = 0; ks < 2; ks++) {
                const uint16_t* Ap = s_ab + (m0 + g) * PA + kb * 32 + ks * 16 + tq;
                uint32_t a0 = *(const uint32_t*)Ap;
                uint32_t a1 = *(const uint32_t*)(Ap + 8 * PA);
                uint32_t a2 = *(const uint32_t*)(Ap + 8);
                uint32_t a3 = *(const uint32_t*)(Ap + 8 * PA + 8);
                const uint16_t* Bp = Wb + ks * 16 + tq;
                #pragma unroll
                for (int j = 0; j < 16; j++) {
                    int n = nh * 128 + j * 8 + g;
                    uint32_t b0 = *(const uint32_t*)(Bp + n * PWT);
                    uint32_t b1 = *(const uint32_t*)(Bp + n * PWT + 8);
                    mma16816(&acc[j * 4], a0, a1, a2, a3, b0, b1);
                }
            }
            __syncthreads();
        }

        #pragma unroll
        for (int j = 0; j < 16; j++) {
            int n = nh * 128 + j * 8 + tq;
            float pb0 = proj_b[n], pb1 = proj_b[n + 1];
            s_x[(m0 + g) * PX + n]         += acc[j * 4 + 0] + pb0;
            s_x[(m0 + g) * PX + n + 1]     += acc[j * 4 + 1] + pb1;
            s_x[(m0 + g + 8) * PX + n]     += acc[j * 4 + 2] + pb0;
            s_x[(m0 + g + 8) * PX + n + 1] += acc[j * 4 + 3] + pb1;
        }
    }
    __syncthreads();

    // ---------- phase 4a: post-LN stats on t (= s_x) ----------
    for (int n = warp; n < 64; n += 8) {
        float s = 0.f, s2 = 0.f;
        #pragma unroll
        for (int j = 0; j < 8; j++) {
            float v = s_x[n * PX + lane + 32 * j];
            s += v; s2 += v * v;
        }
        #pragma unroll
        for (int o = 16; o; o >>= 1) {
            s  += __shfl_xor_sync(0xffffffffu, s,  o);
            s2 += __shfl_xor_sync(0xffffffffu, s2, o);
        }
        float mean = s * (1.f / 256.f);
        if (lane == 0) {
            s_m[n] = mean;
            s_i[n] = rsqrtf(s2 * (1.f / 256.f) - mean * mean + 1e-5f);
        }
    }
    __syncthreads();

    // ---------- phase 4b: y = t + LN(t)*g + b, scatter out ----------
    #pragma unroll 8
    for (int i = 0; i < 64; i++) {
        int idx = tid + i * 256;
        int ch  = idx >> 6;
        int n   = idx & 63;
        float v = s_x[n * PX + ch];
        float y = v + (v - s_m[n]) * s_i[n] * post_g[ch] + post_b[ch];
        Ob[ch * 65536 + (n >> 3) * 256 + (n & 7)] = y;
    }
}

extern "C" void kernel_launch(void* const* d_in, const int* in_sizes, int n_in,
                              void* d_out, int out_size) {
    const float* X      = (const float*)d_in[0];
    const float* pre_g  = (const float*)d_in[1];
    const float* pre_b  = (const float*)d_in[2];
    const float* post_g = (const float*)d_in[3];
    const float* post_b = (const float*)d_in[4];
    const float* qkv_w  = (const float*)d_in[5];
    const float* qkv_b  = (const float*)d_in[6];
    const float* proj_w = (const float*)d_in[7];
    const float* proj_b = (const float*)d_in[8];
    const float* rtab   = (const float*)d_in[9];
    const int*   ridx   = (const int*)d_in[10];
    float* out = (float*)d_out;

    const int smem_bytes = SMEM_FLOATS * 4;
    cudaFuncSetAttribute(window_attn_kernel,
                         cudaFuncAttributeMaxDynamicSharedMemorySize, smem_bytes);

    prep_bias<<<256, 256>>>(rtab, ridx);
    prep_wq<<<768, 256>>>(qkv_w);
    prep_wp<<<256, 256>>>(proj_w);
    window_attn_kernel<<<2048, 256, smem_bytes>>>(
        X, pre_g, pre_b, post_g, post_b, qkv_b, proj_b, out);
}

// round 8
// speedup vs baseline: 18.7529x; 1.2955x over previous
#include <cuda_runtime.h>
#include <cuda_bf16.h>
#include <cstdint>

#define HEADS 16
#define NW 64
#define CH 256
#define PA 264      // pitch (halves) for bf16 activation buffers [64 x 256]
#define PWT 40      // pitch (halves) qkv weight tiles [192 x 32]
#define PWP 24      // pitch (halves) proj weight tiles [256 x 16]
#define PQK 20      // pitch (halves) q/k head tiles [64 x 16]
#define PVT 72      // pitch (halves) vT head tiles [16 x 64]

// smem float offsets
#define OFF_AN 0        // s_an: bf16 [64][264] = 8448 fl
#define OFF_AB 8448     // s_ab: bf16 [64][264] = 8448 fl
#define OFF_R  16896    // region: qkv W 2x(192*40)h | tiles qhat/khat/vT | proj W 2x(256*24)h = 7680 fl
#define OFF_MI 24576    // s_m[64], s_i[64]
#define OFF_RED 24704   // s_red float2[128]
#define SMEM_FLOATS 24960

__device__ __nv_bfloat16 g_biasb[HEADS * NW * NW];
__device__ __nv_bfloat16 g_wq[4 * 8 * 192 * 32];   // [pass][kb][n(192)][k(32)]
__device__ __nv_bfloat16 g_wp[16 * 256 * 16];      // [kb][n(256)][k(16)]

__global__ void prep_bias(const float* __restrict__ table,
                          const int* __restrict__ ridx) {
    int t = blockIdx.x * blockDim.x + threadIdx.x;
    if (t < HEADS * NW * NW) {
        int h = t >> 12;
        int ij = t & 4095;
        g_biasb[t] = __float2bfloat16(table[ridx[ij] * HEADS + h]);
    }
}
__global__ void prep_wq(const float* __restrict__ qkv_w) {
    int t = blockIdx.x * blockDim.x + threadIdx.x;
    if (t >= 4 * 49152) return;
    int p = t / 49152, r = t % 49152;
    int kb = r / 6144, r2 = r % 6144;
    int n = r2 / 32, k = r2 % 32;
    int gcol = (n >> 6) * 256 + p * 64 + (n & 63);
    g_wq[t] = __float2bfloat16(qkv_w[(kb * 32 + k) * 768 + gcol]);
}
__global__ void prep_wp(const float* __restrict__ proj_w) {
    int t = blockIdx.x * blockDim.x + threadIdx.x;
    if (t >= 16 * 4096) return;
    int kb = t / 4096, r = t % 4096;
    int n = r / 16, k = r % 16;
    g_wp[t] = __float2bfloat16(proj_w[(kb * 16 + k) * 256 + n]);
}

__device__ __forceinline__ void cp16s(void* dst, const void* src) {
    uint32_t d = (uint32_t)__cvta_generic_to_shared(dst);
    asm volatile("cp.async.ca.shared.global [%0], [%1], 16;" :: "r"(d), "l"(src));
}
__device__ __forceinline__ void cp_commit() { asm volatile("cp.async.commit_group;"); }
__device__ __forceinline__ void cp_wait1()  { asm volatile("cp.async.wait_group 1;"); }
__device__ __forceinline__ void cp_wait0()  { asm volatile("cp.async.wait_group 0;"); }

__device__ __forceinline__ void mma16816(float* c, uint32_t a0, uint32_t a1,
                                         uint32_t a2, uint32_t a3,
                                         uint32_t b0, uint32_t b1) {
    asm volatile("mma.sync.aligned.m16n8k16.row.col.f32.bf16.bf16.f32 "
        "{%0,%1,%2,%3}, {%4,%5,%6,%7}, {%8,%9}, {%0,%1,%2,%3};"
        : "+f"(c[0]), "+f"(c[1]), "+f"(c[2]), "+f"(c[3])
        : "r"(a0), "r"(a1), "r"(a2), "r"(a3), "r"(b0), "r"(b1));
}
__device__ __forceinline__ uint32_t pack2(float lo, float hi) {
    __nv_bfloat162 h = __floats2bfloat162_rn(lo, hi);
    return *(uint32_t*)&h;
}
__device__ __forceinline__ float2 unpack2(uint32_t u) {
    __nv_bfloat162 h = *(__nv_bfloat162*)&u;
    return make_float2(__bfloat162float(h.x), __bfloat162float(h.y));
}
__device__ __forceinline__ uint16_t bfr(float v) {
    __nv_bfloat16 h = __float2bfloat16(v);
    return *(uint16_t*)&h;
}

__global__ __launch_bounds__(256, 2)
void window_attn_kernel(const float* __restrict__ X,
                        const float* __restrict__ pre_g, const float* __restrict__ pre_b,
                        const float* __restrict__ post_g, const float* __restrict__ post_b,
                        const float* __restrict__ qkv_b, const float* __restrict__ proj_b,
                        float* __restrict__ out) {
    extern __shared__ float sm[];
    uint16_t*  s_an = (uint16_t*)(sm + OFF_AN);
    uint16_t*  s_ab = (uint16_t*)(sm + OFF_AB);
    uint16_t*  s_R  = (uint16_t*)(sm + OFF_R);
    uint16_t*  s_qt = s_R;                 // [4][64][20]
    uint16_t*  s_kt = s_R + 5120;          // [4][64][20]
    uint16_t*  s_vt = s_R + 10240;         // [4][16][72]
    float*     s_m  = sm + OFF_MI;
    float*     s_i  = sm + OFF_MI + 64;
    float2*    s_red = (float2*)(sm + OFF_RED);

    const int w    = blockIdx.x;
    const int b    = w >> 10;
    const int hi   = (w >> 5) & 31;
    const int wi   = w & 31;
    const int tid  = threadIdx.x;
    const int lane = tid & 31;
    const int warp = tid >> 5;

    const float* Xb = X + (size_t)b * (CH * 65536) + hi * 8 * 256 + wi * 8;
    float*       Ob = out + (size_t)b * (CH * 65536) + hi * 8 * 256 + wi * 8;

    // kick pass-0 qkv W tile early (overlaps with LN)
    #pragma unroll
    for (int i = 0; i < 3; i++) {
        int idx = tid + i * 256;
        int n = idx >> 2, kc = (idx & 3) * 8;
        cp16s(s_R + n * PWT + kc, g_wq + n * 32 + kc);
    }
    cp_commit();

    // ---------- phase 0: pre-LN from global, X kept in registers ----------
    {
        const int n0 = tid >> 2;       // token 0..63
        const int cb = tid & 3;        // channel group (ch = cb + 4i)
        float v[64];
        float s = 0.f, s2 = 0.f;
        const float* Xt = Xb + (n0 >> 3) * 256 + (n0 & 7);
        #pragma unroll
        for (int i = 0; i < 64; i++) {
            v[i] = Xt[(size_t)(cb + 4 * i) * 65536];
            s += v[i]; s2 += v[i] * v[i];
        }
        s  += __shfl_xor_sync(0xffffffffu, s, 1);
        s  += __shfl_xor_sync(0xffffffffu, s, 2);
        s2 += __shfl_xor_sync(0xffffffffu, s2, 1);
        s2 += __shfl_xor_sync(0xffffffffu, s2, 2);
        float mean = s * (1.f / 256.f);
        float inv  = rsqrtf(s2 * (1.f / 256.f) - mean * mean + 1e-5f);
        #pragma unroll
        for (int i = 0; i < 64; i++) {
            int c = cb + 4 * i;
            float y = (v[i] - mean) * inv * pre_g[c] + pre_b[c];
            s_an[n0 * PA + c] = bfr(y);
        }
    }
    __syncthreads();

    // mma thread mapping
    const int g   = lane >> 2;          // 0..7
    const int tq  = (lane & 3) * 2;     // 0,2,4,6
    const int m0  = (warp & 3) * 16;    // GEMM m-tile
    const int nh  = warp >> 2;          // GEMM n-half
    const int r0  = m0 + g, r1 = m0 + g + 8;

    // ---------- phase 2: 4 passes of (qkv HMMA -> reg-epilogue -> HMMA attention) ----------
    #pragma unroll 1
    for (int p = 0; p < 4; p++) {
        float acc[48];
        #pragma unroll
        for (int i = 0; i < 48; i++) acc[i] = 0.f;

        const __nv_bfloat16* gw = g_wq + p * 49152;
        if (p > 0) {   // pass-0 prologue already issued pre-LN
            #pragma unroll
            for (int i = 0; i < 3; i++) {
                int idx = tid + i * 256;
                int n = idx >> 2, kc = (idx & 3) * 8;
                cp16s(s_R + n * PWT + kc, gw + n * 32 + kc);
            }
            cp_commit();
        }

        #pragma unroll 1
        for (int kb = 0; kb < 8; kb++) {
            if (kb < 7) {
                const __nv_bfloat16* gwn = gw + (kb + 1) * 6144;
                uint16_t* dstb = s_R + ((kb + 1) & 1) * 7680;
                #pragma unroll
                for (int i = 0; i < 3; i++) {
                    int idx = tid + i * 256;
                    int n = idx >> 2, kc = (idx & 3) * 8;
                    cp16s(dstb + n * PWT + kc, gwn + n * 32 + kc);
                }
                cp_commit();
                cp_wait1();
            } else {
                cp_wait0();
            }
            __syncthreads();
            const uint16_t* Wb = s_R + (kb & 1) * 7680;
            #pragma unroll
            for (int ks = 0; ks < 2; ks++) {
                const uint16_t* Ap = s_an + r0 * PA + kb * 32 + ks * 16 + tq;
                uint32_t a0 = *(const uint32_t*)Ap;
                uint32_t a1 = *(const uint32_t*)(Ap + 8 * PA);
                uint32_t a2 = *(const uint32_t*)(Ap + 8);
                uint32_t a3 = *(const uint32_t*)(Ap + 8 * PA + 8);
                const uint16_t* Bp = Wb + ks * 16 + tq;
                #pragma unroll
                for (int j = 0; j < 12; j++) {
                    int n = nh * 96 + j * 8 + g;
                    uint32_t b0 = *(const uint32_t*)(Bp + n * PWT);
                    uint32_t b1 = *(const uint32_t*)(Bp + n * PWT + 8);
                    mma16816(&acc[j * 4], a0, a1, a2, a3, b0, b1);
                }
            }
            __syncthreads();
        }

        // ---- register epilogue: bias + l2norm (quad shuffles) -> bf16 tiles ----
        if (nh == 0) {
            // q heads 0..3 (j = 2hh, 2hh+1)
            #pragma unroll
            for (int hh = 0; hh < 4; hh++) {
                float tv[2][4];
                float sq0 = 0.f, sq1 = 0.f;
                #pragma unroll
                for (int jj = 0; jj < 2; jj++) {
                    int j = 2 * hh + jj;
                    int n = j * 8 + tq;
                    float b0 = qkv_b[p * 64 + n], b1 = qkv_b[p * 64 + n + 1];
                    tv[jj][0] = acc[j * 4 + 0] + b0;
                    tv[jj][1] = acc[j * 4 + 1] + b1;
                    tv[jj][2] = acc[j * 4 + 2] + b0;
                    tv[jj][3] = acc[j * 4 + 3] + b1;
                    sq0 += tv[jj][0] * tv[jj][0] + tv[jj][1] * tv[jj][1];
                    sq1 += tv[jj][2] * tv[jj][2] + tv[jj][3] * tv[jj][3];
                }
                sq0 += __shfl_xor_sync(0xffffffffu, sq0, 1);
                sq0 += __shfl_xor_sync(0xffffffffu, sq0, 2);
                sq1 += __shfl_xor_sync(0xffffffffu, sq1, 1);
                sq1 += __shfl_xor_sync(0xffffffffu, sq1, 2);
                float rq0 = 1.f / fmaxf(sqrtf(sq0), 1e-12f);
                float rq1 = 1.f / fmaxf(sqrtf(sq1), 1e-12f);
                #pragma unroll
                for (int jj = 0; jj < 2; jj++) {
                    int d = jj * 8 + tq;
                    *(uint32_t*)(s_qt + (hh * 64 + r0) * PQK + d) = pack2(tv[jj][0] * rq0, tv[jj][1] * rq0);
                    *(uint32_t*)(s_qt + (hh * 64 + r1) * PQK + d) = pack2(tv[jj][2] * rq1, tv[jj][3] * rq1);
                }
            }
            // k heads 0,1 (j = 8+2hh, 9+2hh)
            #pragma unroll
            for (int hh = 0; hh < 2; hh++) {
                float tv[2][4];
                float sk0 = 0.f, sk1 = 0.f;
                #pragma unroll
                for (int jj = 0; jj < 2; jj++) {
                    int j = 8 + 2 * hh + jj;
                    int nn = (j - 8) * 8 + tq;
                    float b0 = qkv_b[256 + p * 64 + nn], b1 = qkv_b[256 + p * 64 + nn + 1];
                    tv[jj][0] = acc[j * 4 + 0] + b0;
                    tv[jj][1] = acc[j * 4 + 1] + b1;
                    tv[jj][2] = acc[j * 4 + 2] + b0;
                    tv[jj][3] = acc[j * 4 + 3] + b1;
                    sk0 += tv[jj][0] * tv[jj][0] + tv[jj][1] * tv[jj][1];
                    sk1 += tv[jj][2] * tv[jj][2] + tv[jj][3] * tv[jj][3];
                }
                sk0 += __shfl_xor_sync(0xffffffffu, sk0, 1);
                sk0 += __shfl_xor_sync(0xffffffffu, sk0, 2);
                sk1 += __shfl_xor_sync(0xffffffffu, sk1, 1);
                sk1 += __shfl_xor_sync(0xffffffffu, sk1, 2);
                float rk0 = 1.f / fmaxf(sqrtf(sk0), 1e-12f);
                float rk1 = 1.f / fmaxf(sqrtf(sk1), 1e-12f);
                #pragma unroll
                for (int jj = 0; jj < 2; jj++) {
                    int d = jj * 8 + tq;
                    *(uint32_t*)(s_kt + (hh * 64 + r0) * PQK + d) = pack2(tv[jj][0] * rk0, tv[jj][1] * rk0);
                    *(uint32_t*)(s_kt + (hh * 64 + r1) * PQK + d) = pack2(tv[jj][2] * rk1, tv[jj][3] * rk1);
                }
            }
        } else {
            // k heads 2,3 (j = 2hh, 2hh+1; cols 96..127)
            #pragma unroll
            for (int hh = 0; hh < 2; hh++) {
                float tv[2][4];
                float sk0 = 0.f, sk1 = 0.f;
                #pragma unroll
                for (int jj = 0; jj < 2; jj++) {
                    int j = 2 * hh + jj;
                    int nn = 32 + j * 8 + tq;
                    float b0 = qkv_b[256 + p * 64 + nn], b1 = qkv_b[256 + p * 64 + nn + 1];
                    tv[jj][0] = acc[j * 4 + 0] + b0;
                    tv[jj][1] = acc[j * 4 + 1] + b1;
                    tv[jj][2] = acc[j * 4 + 2] + b0;
                    tv[jj][3] = acc[j * 4 + 3] + b1;
                    sk0 += tv[jj][0] * tv[jj][0] + tv[jj][1] * tv[jj][1];
                    sk1 += tv[jj][2] * tv[jj][2] + tv[jj][3] * tv[jj][3];
                }
                sk0 += __shfl_xor_sync(0xffffffffu, sk0, 1);
                sk0 += __shfl_xor_sync(0xffffffffu, sk0, 2);
                sk1 += __shfl_xor_sync(0xffffffffu, sk1, 1);
                sk1 += __shfl_xor_sync(0xffffffffu, sk1, 2);
                float rk0 = 1.f / fmaxf(sqrtf(sk0), 1e-12f);
                float rk1 = 1.f / fmaxf(sqrtf(sk1), 1e-12f);
                #pragma unroll
                for (int jj = 0; jj < 2; jj++) {
                    int d = jj * 8 + tq;
                    *(uint32_t*)(s_kt + ((2 + hh) * 64 + r0) * PQK + d) = pack2(tv[jj][0] * rk0, tv[jj][1] * rk0);
                    *(uint32_t*)(s_kt + ((2 + hh) * 64 + r1) * PQK + d) = pack2(tv[jj][2] * rk1, tv[jj][3] * rk1);
                }
            }
            // v heads 0..3 (j = 4..11; cols 128..191) -> transposed vT
            #pragma unroll
            for (int j = 4; j < 12; j++) {
                int hv = (j - 4) >> 1;
                int dv = ((j - 4) & 1) * 8 + tq;
                int nn = (j - 4) * 8 + tq;
                float b0 = qkv_b[512 + p * 64 + nn], b1 = qkv_b[512 + p * 64 + nn + 1];
                uint16_t* vp = s_vt + (hv * 16 + dv) * PVT;
                vp[r0]       = bfr(acc[j * 4 + 0] + b0);
                vp[PVT + r0] = bfr(acc[j * 4 + 1] + b1);
                vp[r1]       = bfr(acc[j * 4 + 2] + b0);
                vp[PVT + r1] = bfr(acc[j * 4 + 3] + b1);
            }
        }
        __syncthreads();

        // ---- HMMA attention: warp -> (head wh, row-half mh), bias from L2 ----
        {
            const int wh = warp >> 1, mh = warp & 1;
            const uint16_t* qh = s_qt + wh * 64 * PQK;
            const uint16_t* kh = s_kt + wh * 64 * PQK;
            const uint16_t* vh = s_vt + wh * 16 * PVT;
            const uint32_t* gb = (const uint32_t*)g_biasb + (p * 4 + wh) * 2048;

            uint32_t kb0[8], kb1[8];
            #pragma unroll
            for (int j = 0; j < 8; j++) {
                kb0[j] = *(const uint32_t*)(kh + (j * 8 + g) * PQK + tq);
                kb1[j] = *(const uint32_t*)(kh + (j * 8 + g) * PQK + tq + 8);
            }

            #pragma unroll
            for (int t = 0; t < 2; t++) {
                int r = mh * 32 + t * 16;
                uint32_t qa0 = *(const uint32_t*)(qh + (r + g) * PQK + tq);
                uint32_t qa1 = *(const uint32_t*)(qh + (r + g + 8) * PQK + tq);
                uint32_t qa2 = *(const uint32_t*)(qh + (r + g) * PQK + tq + 8);
                uint32_t qa3 = *(const uint32_t*)(qh + (r + g + 8) * PQK + tq + 8);

                float Sc[8][4];
                #pragma unroll
                for (int j = 0; j < 8; j++) {
                    float2 f0 = unpack2(gb[(r + g) * 32 + j * 4 + (tq >> 1)]);
                    float2 f1 = unpack2(gb[(r + g + 8) * 32 + j * 4 + (tq >> 1)]);
                    Sc[j][0] = f0.x; Sc[j][1] = f0.y;
                    Sc[j][2] = f1.x; Sc[j][3] = f1.y;
                }
                #pragma unroll
                for (int j = 0; j < 8; j++)
                    mma16816(Sc[j], qa0, qa1, qa2, qa3, kb0[j], kb1[j]);

                float su0 = 0.f, su1 = 0.f;
                #pragma unroll
                for (int j = 0; j < 8; j++) {
                    Sc[j][0] = __expf(Sc[j][0]);
                    Sc[j][1] = __expf(Sc[j][1]);
                    Sc[j][2] = __expf(Sc[j][2]);
                    Sc[j][3] = __expf(Sc[j][3]);
                    su0 += Sc[j][0] + Sc[j][1];
                    su1 += Sc[j][2] + Sc[j][3];
                }
                su0 += __shfl_xor_sync(0xffffffffu, su0, 1);
                su0 += __shfl_xor_sync(0xffffffffu, su0, 2);
                su1 += __shfl_xor_sync(0xffffffffu, su1, 1);
                su1 += __shfl_xor_sync(0xffffffffu, su1, 2);
                float inv0 = 1.f / su0, inv1 = 1.f / su1;

                float Oc[2][4];
                #pragma unroll
                for (int nt = 0; nt < 2; nt++)
                    #pragma unroll
                    for (int i = 0; i < 4; i++) Oc[nt][i] = 0.f;

                #pragma unroll
                for (int ks = 0; ks < 4; ks++) {
                    uint32_t pa0 = pack2(Sc[2 * ks][0] * inv0,     Sc[2 * ks][1] * inv0);
                    uint32_t pa1 = pack2(Sc[2 * ks][2] * inv1,     Sc[2 * ks][3] * inv1);
                    uint32_t pa2 = pack2(Sc[2 * ks + 1][0] * inv0, Sc[2 * ks + 1][1] * inv0);
                    uint32_t pa3 = pack2(Sc[2 * ks + 1][2] * inv1, Sc[2 * ks + 1][3] * inv1);
                    #pragma unroll
                    for (int nt = 0; nt < 2; nt++) {
                        uint32_t vb0 = *(const uint32_t*)(vh + (nt * 8 + g) * PVT + ks * 16 + tq);
                        uint32_t vb1 = *(const uint32_t*)(vh + (nt * 8 + g) * PVT + ks * 16 + tq + 8);
                        mma16816(Oc[nt], pa0, pa1, pa2, pa3, vb0, vb1);
                    }
                }

                int hc = (p * 4 + wh) * 16;
                #pragma unroll
                for (int nt = 0; nt < 2; nt++) {
                    *(uint32_t*)(s_ab + (r + g) * PA + hc + nt * 8 + tq)     = pack2(Oc[nt][0], Oc[nt][1]);
                    *(uint32_t*)(s_ab + (r + g + 8) * PA + hc + nt * 8 + tq) = pack2(Oc[nt][2], Oc[nt][3]);
                }
            }
        }
        __syncthreads();
    }

    // ---------- phase 3: proj HMMA (k-chunks of 16, double buffered in R) ----------
    float acc[64];
    #pragma unroll
    for (int i = 0; i < 64; i++) acc[i] = 0.f;

    #pragma unroll
    for (int i = 0; i < 2; i++) {
        int idx = tid + i * 256;
        int n = idx >> 1, kc = (idx & 1) * 8;
        cp16s(s_R + n * PWP + kc, g_wp + n * 16 + kc);
    }
    cp_commit();

    #pragma unroll 1
    for (int kb = 0; kb < 16; kb++) {
        if (kb < 15) {
            const __nv_bfloat16* gwn = g_wp + (kb + 1) * 4096;
            uint16_t* dstb = s_R + ((kb + 1) & 1) * 6144;
            #pragma unroll
            for (int i = 0; i < 2; i++) {
                int idx = tid + i * 256;
                int n = idx >> 1, kc = (idx & 1) * 8;
                cp16s(dstb + n * PWP + kc, gwn + n * 16 + kc);
            }
            cp_commit();
            cp_wait1();
        } else {
            cp_wait0();
        }
        __syncthreads();
        const uint16_t* Wb = s_R + (kb & 1) * 6144;
        const uint16_t* Ap = s_ab + r0 * PA + kb * 16 + tq;
        uint32_t a0 = *(const uint32_t*)Ap;
        uint32_t a1 = *(const uint32_t*)(Ap + 8 * PA);
        uint32_t a2 = *(const uint32_t*)(Ap + 8);
        uint32_t a3 = *(const uint32_t*)(Ap + 8 * PA + 8);
        #pragma unroll
        for (int j = 0; j < 16; j++) {
            int n = nh * 128 + j * 8 + g;
            uint32_t b0 = *(const uint32_t*)(Wb + n * PWP + tq);
            uint32_t b1 = *(const uint32_t*)(Wb + n * PWP + 8 + tq);
            mma16816(&acc[j * 4], a0, a1, a2, a3, b0, b1);
        }
        __syncthreads();
    }

    // ---------- phase 4: t = proj + bias + x (regs); post-LN; scatter out ----------
    {
        const int xo0 = (r0 >> 3) * 256 + (r0 & 7);
        const int xo1 = (r1 >> 3) * 256 + (r1 & 7);
        float s0 = 0.f, s20 = 0.f, s1 = 0.f, s21 = 0.f;
        #pragma unroll
        for (int j = 0; j < 16; j++) {
            int c = nh * 128 + j * 8 + tq;
            float pb0 = proj_b[c], pb1 = proj_b[c + 1];
            float x00 = Xb[(size_t)c * 65536 + xo0];
            float x01 = Xb[(size_t)(c + 1) * 65536 + xo0];
            float x10 = Xb[(size_t)c * 65536 + xo1];
            float x11 = Xb[(size_t)(c + 1) * 65536 + xo1];
            acc[j * 4 + 0] += pb0 + x00;
            acc[j * 4 + 1] += pb1 + x01;
            acc[j * 4 + 2] += pb0 + x10;
            acc[j * 4 + 3] += pb1 + x11;
            s0  += acc[j * 4 + 0] + acc[j * 4 + 1];
            s20 += acc[j * 4 + 0] * acc[j * 4 + 0] + acc[j * 4 + 1] * acc[j * 4 + 1];
            s1  += acc[j * 4 + 2] + acc[j * 4 + 3];
            s21 += acc[j * 4 + 2] * acc[j * 4 + 2] + acc[j * 4 + 3] * acc[j * 4 + 3];
        }
        s0  += __shfl_xor_sync(0xffffffffu, s0, 1);
        s0  += __shfl_xor_sync(0xffffffffu, s0, 2);
        s20 += __shfl_xor_sync(0xffffffffu, s20, 1);
        s20 += __shfl_xor_sync(0xffffffffu, s20, 2);
        s1  += __shfl_xor_sync(0xffffffffu, s1, 1);
        s1  += __shfl_xor_sync(0xffffffffu, s1, 2);
        s21 += __shfl_xor_sync(0xffffffffu, s21, 1);
        s21 += __shfl_xor_sync(0xffffffffu, s21, 2);
        if (tq == 0) {
            s_red[r0 * 2 + nh] = make_float2(s0, s20);
            s_red[r1 * 2 + nh] = make_float2(s1, s21);
        }
        __syncthreads();
        if (tid < 64) {
            float2 a = s_red[tid * 2], bb = s_red[tid * 2 + 1];
            float ts = a.x + bb.x, ts2 = a.y + bb.y;
            float mean = ts * (1.f / 256.f);
            s_m[tid] = mean;
            s_i[tid] = rsqrtf(ts2 * (1.f / 256.f) - mean * mean + 1e-5f);
        }
        __syncthreads();

        float mm0 = s_m[r0], ii0 = s_i[r0];
        float mm1 = s_m[r1], ii1 = s_i[r1];
        #pragma unroll
        for (int j = 0; j < 16; j++) {
            int c = nh * 128 + j * 8 + tq;
            float pg0 = post_g[c], pg1 = post_g[c + 1];
            float pbb0 = post_b[c], pbb1 = post_b[c + 1];
            float t00 = acc[j * 4 + 0], t01 = acc[j * 4 + 1];
            float t10 = acc[j * 4 + 2], t11 = acc[j * 4 + 3];
            Ob[(size_t)c * 65536 + xo0]       = t00 + (t00 - mm0) * ii0 * pg0 + pbb0;
            Ob[(size_t)(c + 1) * 65536 + xo0] = t01 + (t01 - mm0) * ii0 * pg1 + pbb1;
            Ob[(size_t)c * 65536 + xo1]       = t10 + (t10 - mm1) * ii1 * pg0 + pbb0;
            Ob[(size_t)(c + 1) * 65536 + xo1] = t11 + (t11 - mm1) * ii1 * pg1 + pbb1;
        }
    }
}

extern "C" void kernel_launch(void* const* d_in, const int* in_sizes, int n_in,
                              void* d_out, int out_size) {
    const float* X      = (const float*)d_in[0];
    const float* pre_g  = (const float*)d_in[1];
    const float* pre_b  = (const float*)d_in[2];
    const float* post_g = (const float*)d_in[3];
    const float* post_b = (const float*)d_in[4];
    const float* qkv_w  = (const float*)d_in[5];
    const float* qkv_b  = (const float*)d_in[6];
    const float* proj_w = (const float*)d_in[7];
    const float* proj_b = (const float*)d_in[8];
    const float* rtab   = (const float*)d_in[9];
    const int*   ridx   = (const int*)d_in[10];
    float* out = (float*)d_out;

    const int smem_bytes = SMEM_FLOATS * 4;   // 99,840 B -> 2 CTAs/SM
    cudaFuncSetAttribute(window_attn_kernel,
                         cudaFuncAttributeMaxDynamicSharedMemorySize, smem_bytes);

    prep_bias<<<256, 256>>>(rtab, ridx);
    prep_wq<<<768, 256>>>(qkv_w);
    prep_wp<<<256, 256>>>(proj_w);
    window_attn_kernel<<<2048, 256, smem_bytes>>>(
        X, pre_g, pre_b, post_g, post_b, qkv_b, proj_b, out);
}

// round 9
// speedup vs baseline: 21.2329x; 1.1322x over previous
#include <cuda_runtime.h>
#include <cuda_bf16.h>
#include <cstdint>

#define HEADS 16
#define NW 64
#define CH 256
#define PA 264      // pitch (halves) bf16 activation buffers [64 x 256]; w=132 (==4 mod 32)
#define PWT 40      // pitch (halves) qkv weight tiles [192 x 32]; w=20
#define PWP 24      // pitch (halves) proj weight tiles [256 x 16]; w=12
#define PQK 24      // pitch (halves) q/k head tiles [64 x 16]; w=12
#define PVT 72      // pitch (halves) vT head tiles [16 x 64]; w=36 (==4 mod 32)

// smem float offsets
#define OFF_AN 0        // s_an: bf16 [64][264] = 8448 fl
#define OFF_AB 8448     // s_ab: bf16 [64][264] = 8448 fl
#define OFF_R  16896    // region: qkv W 2x(192*40)h=15360h | q 6144h + k 6144h + vT 4608h = 16896h | proj W 2x(256*24)h=12288h -> 8448 fl
#define OFF_MI 25344    // s_m[64], s_i[64]
#define OFF_RED 25472   // s_red float2[64][4] = 512 fl
#define SMEM_FLOATS 25984

__device__ __nv_bfloat16 g_biasb[HEADS * NW * NW];
__device__ __nv_bfloat16 g_wq[4 * 8 * 192 * 32];   // [pass][kb][n(192)][k(32)]
__device__ __nv_bfloat16 g_wp[16 * 256 * 16];      // [kb][n(256)][k(16)]

__global__ void prep_bias(const float* __restrict__ table,
                          const int* __restrict__ ridx) {
    int t = blockIdx.x * blockDim.x + threadIdx.x;
    if (t < HEADS * NW * NW) {
        int h = t >> 12;
        int ij = t & 4095;
        g_biasb[t] = __float2bfloat16(table[ridx[ij] * HEADS + h]);
    }
}
__global__ void prep_wq(const float* __restrict__ qkv_w) {
    int t = blockIdx.x * blockDim.x + threadIdx.x;
    if (t >= 4 * 49152) return;
    int p = t / 49152, r = t % 49152;
    int kb = r / 6144, r2 = r % 6144;
    int n = r2 / 32, k = r2 % 32;
    int gcol = (n >> 6) * 256 + p * 64 + (n & 63);
    g_wq[t] = __float2bfloat16(qkv_w[(kb * 32 + k) * 768 + gcol]);
}
__global__ void prep_wp(const float* __restrict__ proj_w) {
    int t = blockIdx.x * blockDim.x + threadIdx.x;
    if (t >= 16 * 4096) return;
    int kb = t / 4096, r = t % 4096;
    int n = r / 16, k = r % 16;
    g_wp[t] = __float2bfloat16(proj_w[(kb * 16 + k) * 256 + n]);
}

__device__ __forceinline__ void cp16s(void* dst, const void* src) {
    uint32_t d = (uint32_t)__cvta_generic_to_shared(dst);
    asm volatile("cp.async.cg.shared.global [%0], [%1], 16;" :: "r"(d), "l"(src));
}
__device__ __forceinline__ void cp_commit() { asm volatile("cp.async.commit_group;"); }
__device__ __forceinline__ void cp_wait1()  { asm volatile("cp.async.wait_group 1;"); }
__device__ __forceinline__ void cp_wait0()  { asm volatile("cp.async.wait_group 0;"); }

__device__ __forceinline__ uint32_t SAu(const void* p) {
    return (uint32_t)__cvta_generic_to_shared(p);
}
__device__ __forceinline__ void ldsm4(uint32_t* r, uint32_t a) {
    asm volatile("ldmatrix.sync.aligned.m8n8.x4.shared.b16 {%0,%1,%2,%3}, [%4];"
        : "=r"(r[0]), "=r"(r[1]), "=r"(r[2]), "=r"(r[3]) : "r"(a));
}
__device__ __forceinline__ void stsm4(uint32_t a, uint32_t r0, uint32_t r1,
                                      uint32_t r2, uint32_t r3) {
    asm volatile("stmatrix.sync.aligned.m8n8.x4.shared.b16 [%0], {%1,%2,%3,%4};"
        :: "r"(a), "r"(r0), "r"(r1), "r"(r2), "r"(r3) : "memory");
}
__device__ __forceinline__ void mma16816(float* c, uint32_t a0, uint32_t a1,
                                         uint32_t a2, uint32_t a3,
                                         uint32_t b0, uint32_t b1) {
    asm volatile("mma.sync.aligned.m16n8k16.row.col.f32.bf16.bf16.f32 "
        "{%0,%1,%2,%3}, {%4,%5,%6,%7}, {%8,%9}, {%0,%1,%2,%3};"
        : "+f"(c[0]), "+f"(c[1]), "+f"(c[2]), "+f"(c[3])
        : "r"(a0), "r"(a1), "r"(a2), "r"(a3), "r"(b0), "r"(b1));
}
__device__ __forceinline__ uint32_t pack2(float lo, float hi) {
    __nv_bfloat162 h = __floats2bfloat162_rn(lo, hi);
    return *(uint32_t*)&h;
}
__device__ __forceinline__ float2 unpack2(uint32_t u) {
    __nv_bfloat162 h = *(__nv_bfloat162*)&u;
    return make_float2(__bfloat162float(h.x), __bfloat162float(h.y));
}
__device__ __forceinline__ uint16_t bfr(float v) {
    __nv_bfloat16 h = __float2bfloat16(v);
    return *(uint16_t*)&h;
}

__global__ __launch_bounds__(256, 2)
void window_attn_kernel(const float* __restrict__ X,
                        const float* __restrict__ pre_g, const float* __restrict__ pre_b,
                        const float* __restrict__ post_g, const float* __restrict__ post_b,
                        const float* __restrict__ qkv_b, const float* __restrict__ proj_b,
                        float* __restrict__ out) {
    extern __shared__ float sm[];
    uint16_t*  s_an = (uint16_t*)(sm + OFF_AN);
    uint16_t*  s_ab = (uint16_t*)(sm + OFF_AB);
    uint16_t*  s_R  = (uint16_t*)(sm + OFF_R);
    uint16_t*  s_qt = s_R;                 // [4][64][24]
    uint16_t*  s_kt = s_R + 6144;          // [4][64][24]
    uint16_t*  s_vt = s_R + 12288;         // [4][16][72]
    float*     s_m  = sm + OFF_MI;
    float*     s_i  = sm + OFF_MI + 64;
    float2 (*s_red)[4] = (float2(*)[4])(sm + OFF_RED);

    const uint32_t an_b = SAu(s_an);
    const uint32_t ab_b = SAu(s_ab);
    const uint32_t qt_b = SAu(s_qt);
    const uint32_t kt_b = SAu(s_kt);
    const uint32_t vt_b = SAu(s_vt);

    const int w    = blockIdx.x;
    const int b    = w >> 10;
    const int hi   = (w >> 5) & 31;
    const int wi   = w & 31;
    const int tid  = threadIdx.x;
    const int lane = tid & 31;
    const int warp = tid >> 5;

    const float* Xb = X + (size_t)b * (CH * 65536) + hi * 8 * 256 + wi * 8;
    float*       Ob = out + (size_t)b * (CH * 65536) + hi * 8 * 256 + wi * 8;

    // kick pass-0 qkv W tile early (overlaps with LN)
    #pragma unroll
    for (int i = 0; i < 3; i++) {
        int idx = tid + i * 256;
        int n = idx >> 2, kc = (idx & 3) * 8;
        cp16s(s_R + n * PWT + kc, g_wq + n * 32 + kc);
    }
    cp_commit();

    // ---------- phase 0: pre-LN from global, X kept in registers ----------
    {
        const int n0 = tid >> 2;
        const int cb = tid & 3;
        float v[64];
        float s = 0.f, s2 = 0.f;
        const float* Xt = Xb + (n0 >> 3) * 256 + (n0 & 7);
        #pragma unroll
        for (int i = 0; i < 64; i++) {
            v[i] = Xt[(size_t)(cb + 4 * i) * 65536];
            s += v[i]; s2 += v[i] * v[i];
        }
        s  += __shfl_xor_sync(0xffffffffu, s, 1);
        s  += __shfl_xor_sync(0xffffffffu, s, 2);
        s2 += __shfl_xor_sync(0xffffffffu, s2, 1);
        s2 += __shfl_xor_sync(0xffffffffu, s2, 2);
        float mean = s * (1.f / 256.f);
        float inv  = rsqrtf(s2 * (1.f / 256.f) - mean * mean + 1e-5f);
        #pragma unroll
        for (int i = 0; i < 64; i++) {
            int c = cb + 4 * i;
            float y = (v[i] - mean) * inv * pre_g[c] + pre_b[c];
            s_an[n0 * PA + c] = bfr(y);
        }
    }
    __syncthreads();

    // mma thread mapping
    const int g      = lane >> 2;
    const int tq     = (lane & 3) * 2;
    const int lane15 = lane & 15;
    const int lhi8   = (lane & 16) ? 8 : 0;
    const int brow   = (lane & 7) + lhi8;   // B-fragment row within 16
    const int bk     = (lane & 8) ? 8 : 0;  // B-fragment k-half
    const int m0     = (warp & 1) * 32;     // GEMM m-tile (2-way m split)
    const int nh4    = warp >> 1;           // GEMM n-quarter (4-way n split)

    // ---------- phase 2: 4 passes of (qkv HMMA -> reg epilogue -> HMMA attention) ----------
    #pragma unroll 1
    for (int p = 0; p < 4; p++) {
        float acc[48];
        #pragma unroll
        for (int i = 0; i < 48; i++) acc[i] = 0.f;

        const __nv_bfloat16* gw = g_wq + p * 49152;
        if (p > 0) {
            #pragma unroll
            for (int i = 0; i < 3; i++) {
                int idx = tid + i * 256;
                int n = idx >> 2, kc = (idx & 3) * 8;
                cp16s(s_R + n * PWT + kc, gw + n * 32 + kc);
            }
            cp_commit();
        }

        #pragma unroll 1
        for (int kb = 0; kb < 8; kb++) {
            if (kb < 7) {
                const __nv_bfloat16* gwn = gw + (kb + 1) * 6144;
                uint16_t* dstb = s_R + ((kb + 1) & 1) * 7680;
                #pragma unroll
                for (int i = 0; i < 3; i++) {
                    int idx = tid + i * 256;
                    int n = idx >> 2, kc = (idx & 3) * 8;
                    cp16s(dstb + n * PWT + kc, gwn + n * 32 + kc);
                }
                cp_commit();
                cp_wait1();
            } else {
                cp_wait0();
            }
            __syncthreads();
            const uint32_t wb_b = SAu(s_R + (kb & 1) * 7680);
            #pragma unroll
            for (int ks = 0; ks < 2; ks++) {
                uint32_t Af[2][4];
                #pragma unroll
                for (int mf = 0; mf < 2; mf++)
                    ldsm4(Af[mf], an_b +
                        (((m0 + mf * 16 + lane15) * PA + kb * 32 + ks * 16 + lhi8) << 1));
                uint32_t Bf[6][2];
                #pragma unroll
                for (int jp = 0; jp < 3; jp++) {
                    uint32_t r[4];
                    ldsm4(r, wb_b +
                        (((nh4 * 48 + jp * 16 + brow) * PWT + ks * 16 + bk) << 1));
                    Bf[2 * jp][0] = r[0]; Bf[2 * jp][1] = r[1];
                    Bf[2 * jp + 1][0] = r[2]; Bf[2 * jp + 1][1] = r[3];
                }
                #pragma unroll
                for (int mf = 0; mf < 2; mf++)
                    #pragma unroll
                    for (int j = 0; j < 6; j++)
                        mma16816(&acc[(mf * 6 + j) * 4],
                                 Af[mf][0], Af[mf][1], Af[mf][2], Af[mf][3],
                                 Bf[j][0], Bf[j][1]);
            }
            __syncthreads();
        }

        // ---- register epilogue: bias + l2norm (quad shuffles) -> bf16 tiles ----
        #pragma unroll
        for (int bi = 0; bi < 3; bi++) {
            const int blk = nh4 * 3 + bi;   // 0..3 q heads, 4..7 k heads, 8..11 v heads
            const int jj0 = bi * 2;
            #pragma unroll
            for (int mf = 0; mf < 2; mf++) {
                float tv[2][4];
                #pragma unroll
                for (int jj = 0; jj < 2; jj++) {
                    int nl = nh4 * 48 + (jj0 + jj) * 8 + tq;
                    int gcol = (nl >> 6) * 256 + p * 64 + (nl & 63);
                    float b0 = qkv_b[gcol], b1 = qkv_b[gcol + 1];
                    int ai = (mf * 6 + jj0 + jj) * 4;
                    tv[jj][0] = acc[ai + 0] + b0;
                    tv[jj][1] = acc[ai + 1] + b1;
                    tv[jj][2] = acc[ai + 2] + b0;
                    tv[jj][3] = acc[ai + 3] + b1;
                }
                if (blk < 8) {
                    float s0 = tv[0][0]*tv[0][0] + tv[0][1]*tv[0][1]
                             + tv[1][0]*tv[1][0] + tv[1][1]*tv[1][1];
                    float s1 = tv[0][2]*tv[0][2] + tv[0][3]*tv[0][3]
                             + tv[1][2]*tv[1][2] + tv[1][3]*tv[1][3];
                    s0 += __shfl_xor_sync(0xffffffffu, s0, 1);
                    s0 += __shfl_xor_sync(0xffffffffu, s0, 2);
                    s1 += __shfl_xor_sync(0xffffffffu, s1, 1);
                    s1 += __shfl_xor_sync(0xffffffffu, s1, 2);
                    float r0s = 1.f / fmaxf(sqrtf(s0), 1e-12f);
                    float r1s = 1.f / fmaxf(sqrtf(s1), 1e-12f);
                    int head = blk & 3;
                    uint32_t base = (blk < 4) ? qt_b : kt_b;
                    stsm4(base + (((head * 64 + m0 + mf * 16 + lane15) * PQK + lhi8) << 1),
                          pack2(tv[0][0] * r0s, tv[0][1] * r0s),
                          pack2(tv[0][2] * r1s, tv[0][3] * r1s),
                          pack2(tv[1][0] * r0s, tv[1][1] * r0s),
                          pack2(tv[1][2] * r1s, tv[1][3] * r1s));
                } else {
                    int hv = blk - 8;
                    int rl = m0 + mf * 16 + g, rh = rl + 8;
                    #pragma unroll
                    for (int jj = 0; jj < 2; jj++) {
                        int dv = jj * 8 + tq;
                        uint16_t* vp = s_vt + (hv * 16 + dv) * PVT;
                        vp[rl]       = bfr(tv[jj][0]);
                        vp[PVT + rl] = bfr(tv[jj][1]);
                        vp[rh]       = bfr(tv[jj][2]);
                        vp[PVT + rh] = bfr(tv[jj][3]);
                    }
                }
            }
        }
        __syncthreads();

        // ---- HMMA attention: warp -> (head wh, row-half mh) ----
        {
            const int wh = warp >> 1, mh = warp & 1;
            const uint32_t* gb = (const uint32_t*)g_biasb + (p * 4 + wh) * 2048;

            uint32_t kb0[8], kb1[8];
            #pragma unroll
            for (int jp = 0; jp < 4; jp++) {
                uint32_t r[4];
                ldsm4(r, kt_b + (((wh * 64 + jp * 16 + brow) * PQK + bk) << 1));
                kb0[2 * jp] = r[0]; kb1[2 * jp] = r[1];
                kb0[2 * jp + 1] = r[2]; kb1[2 * jp + 1] = r[3];
            }
            uint32_t vb0[4][2], vb1[4][2];
            #pragma unroll
            for (int ks = 0; ks < 4; ks++) {
                uint32_t r[4];
                ldsm4(r, vt_b + (((wh * 16 + brow) * PVT + ks * 16 + bk) << 1));
                vb0[ks][0] = r[0]; vb1[ks][0] = r[1];
                vb0[ks][1] = r[2]; vb1[ks][1] = r[3];
            }

            #pragma unroll
            for (int t = 0; t < 2; t++) {
                int r = mh * 32 + t * 16;
                uint32_t qa[4];
                ldsm4(qa, qt_b + (((wh * 64 + r + lane15) * PQK + lhi8) << 1));

                float Sc[8][4];
                #pragma unroll
                for (int j = 0; j < 8; j++) {
                    float2 f0 = unpack2(gb[(r + g) * 32 + j * 4 + (tq >> 1)]);
                    float2 f1 = unpack2(gb[(r + g + 8) * 32 + j * 4 + (tq >> 1)]);
                    Sc[j][0] = f0.x; Sc[j][1] = f0.y;
                    Sc[j][2] = f1.x; Sc[j][3] = f1.y;
                }
                #pragma unroll
                for (int j = 0; j < 8; j++)
                    mma16816(Sc[j], qa[0], qa[1], qa[2], qa[3], kb0[j], kb1[j]);

                float su0 = 0.f, su1 = 0.f;
                #pragma unroll
                for (int j = 0; j < 8; j++) {
                    Sc[j][0] = __expf(Sc[j][0]);
                    Sc[j][1] = __expf(Sc[j][1]);
                    Sc[j][2] = __expf(Sc[j][2]);
                    Sc[j][3] = __expf(Sc[j][3]);
                    su0 += Sc[j][0] + Sc[j][1];
                    su1 += Sc[j][2] + Sc[j][3];
                }
                su0 += __shfl_xor_sync(0xffffffffu, su0, 1);
                su0 += __shfl_xor_sync(0xffffffffu, su0, 2);
                su1 += __shfl_xor_sync(0xffffffffu, su1, 1);
                su1 += __shfl_xor_sync(0xffffffffu, su1, 2);
                float inv0 = 1.f / su0, inv1 = 1.f / su1;

                float Oc[2][4];
                #pragma unroll
                for (int nt = 0; nt < 2; nt++)
                    #pragma unroll
                    for (int i = 0; i < 4; i++) Oc[nt][i] = 0.f;

                #pragma unroll
                for (int ks = 0; ks < 4; ks++) {
                    uint32_t pa0 = pack2(Sc[2 * ks][0] * inv0,     Sc[2 * ks][1] * inv0);
                    uint32_t pa1 = pack2(Sc[2 * ks][2] * inv1,     Sc[2 * ks][3] * inv1);
                    uint32_t pa2 = pack2(Sc[2 * ks + 1][0] * inv0, Sc[2 * ks + 1][1] * inv0);
                    uint32_t pa3 = pack2(Sc[2 * ks + 1][2] * inv1, Sc[2 * ks + 1][3] * inv1);
                    #pragma unroll
                    for (int nt = 0; nt < 2; nt++)
                        mma16816(Oc[nt], pa0, pa1, pa2, pa3, vb0[ks][nt], vb1[ks][nt]);
                }

                int hc = (p * 4 + wh) * 16;
                stsm4(ab_b + (((r + lane15) * PA + hc + lhi8) << 1),
                      pack2(Oc[0][0], Oc[0][1]), pack2(Oc[0][2], Oc[0][3]),
                      pack2(Oc[1][0], Oc[1][1]), pack2(Oc[1][2], Oc[1][3]));
            }
        }
        __syncthreads();
    }

    // ---------- phase 3: proj HMMA (k-chunks of 16, double buffered) ----------
    float acc[64];
    #pragma unroll
    for (int i = 0; i < 64; i++) acc[i] = 0.f;

    #pragma unroll
    for (int i = 0; i < 2; i++) {
        int idx = tid + i * 256;
        int n = idx >> 1, kc = (idx & 1) * 8;
        cp16s(s_R + n * PWP + kc, g_wp + n * 16 + kc);
    }
    cp_commit();

    #pragma unroll 1
    for (int kb = 0; kb < 16; kb++) {
        if (kb < 15) {
            const __nv_bfloat16* gwn = g_wp + (kb + 1) * 4096;
            uint16_t* dstb = s_R + ((kb + 1) & 1) * 6144;
            #pragma unroll
            for (int i = 0; i < 2; i++) {
                int idx = tid + i * 256;
                int n = idx >> 1, kc = (idx & 1) * 8;
                cp16s(dstb + n * PWP + kc, gwn + n * 16 + kc);
            }
            cp_commit();
            cp_wait1();
        } else {
            cp_wait0();
        }
        __syncthreads();
        const uint32_t wb_b = SAu(s_R + (kb & 1) * 6144);
        uint32_t Af[2][4];
        #pragma unroll
        for (int mf = 0; mf < 2; mf++)
            ldsm4(Af[mf], ab_b + (((m0 + mf * 16 + lane15) * PA + kb * 16 + lhi8) << 1));
        uint32_t Bf[8][2];
        #pragma unroll
        for (int jp = 0; jp < 4; jp++) {
            uint32_t r[4];
            ldsm4(r, wb_b + (((nh4 * 64 + jp * 16 + brow) * PWP + bk) << 1));
            Bf[2 * jp][0] = r[0]; Bf[2 * jp][1] = r[1];
            Bf[2 * jp + 1][0] = r[2]; Bf[2 * jp + 1][1] = r[3];
        }
        #pragma unroll
        for (int mf = 0; mf < 2; mf++)
            #pragma unroll
            for (int j = 0; j < 8; j++)
                mma16816(&acc[(mf * 8 + j) * 4],
                         Af[mf][0], Af[mf][1], Af[mf][2], Af[mf][3],
                         Bf[j][0], Bf[j][1]);
        __syncthreads();
    }

    // ---------- phase 4: t = proj + bias + x (regs); post-LN; scatter out ----------
    {
        int rows[4], xo[4];
        #pragma unroll
        for (int mf = 0; mf < 2; mf++) {
            rows[mf * 2 + 0] = m0 + mf * 16 + g;
            rows[mf * 2 + 1] = m0 + mf * 16 + g + 8;
        }
        #pragma unroll
        for (int i = 0; i < 4; i++) xo[i] = (rows[i] >> 3) * 256 + (rows[i] & 7);

        float rs[4], rs2[4];
        #pragma unroll
        for (int i = 0; i < 4; i++) { rs[i] = 0.f; rs2[i] = 0.f; }

        #pragma unroll
        for (int mf = 0; mf < 2; mf++)
            #pragma unroll
            for (int j = 0; j < 8; j++) {
                int c = nh4 * 64 + j * 8 + tq;
                int ai = (mf * 8 + j) * 4;
                float pb0 = proj_b[c], pb1 = proj_b[c + 1];
                acc[ai + 0] += pb0 + Xb[(size_t)c * 65536 + xo[mf * 2]];
                acc[ai + 1] += pb1 + Xb[(size_t)(c + 1) * 65536 + xo[mf * 2]];
                acc[ai + 2] += pb0 + Xb[(size_t)c * 65536 + xo[mf * 2 + 1]];
                acc[ai + 3] += pb1 + Xb[(size_t)(c + 1) * 65536 + xo[mf * 2 + 1]];
                rs[mf * 2]      += acc[ai + 0] + acc[ai + 1];
                rs2[mf * 2]     += acc[ai + 0] * acc[ai + 0] + acc[ai + 1] * acc[ai + 1];
                rs[mf * 2 + 1]  += acc[ai + 2] + acc[ai + 3];
                rs2[mf * 2 + 1] += acc[ai + 2] * acc[ai + 2] + acc[ai + 3] * acc[ai + 3];
            }
        #pragma unroll
        for (int i = 0; i < 4; i++) {
            rs[i]  += __shfl_xor_sync(0xffffffffu, rs[i], 1);
            rs[i]  += __shfl_xor_sync(0xffffffffu, rs[i], 2);
            rs2[i] += __shfl_xor_sync(0xffffffffu, rs2[i], 1);
            rs2[i] += __shfl_xor_sync(0xffffffffu, rs2[i], 2);
        }
        if (tq == 0) {
            #pragma unroll
            for (int i = 0; i < 4; i++)
                s_red[rows[i]][nh4] = make_float2(rs[i], rs2[i]);
        }
        __syncthreads();
        if (tid < 64) {
            float ts = 0.f, ts2 = 0.f;
            #pragma unroll
            for (int q4 = 0; q4 < 4; q4++) {
                float2 a = s_red[tid][q4];
                ts += a.x; ts2 += a.y;
            }
            float mean = ts * (1.f / 256.f);
            s_m[tid] = mean;
            s_i[tid] = rsqrtf(ts2 * (1.f / 256.f) - mean * mean + 1e-5f);
        }
        __syncthreads();

        float mm[4], ii[4];
        #pragma unroll
        for (int i = 0; i < 4; i++) { mm[i] = s_m[rows[i]]; ii[i] = s_i[rows[i]]; }

        #pragma unroll
        for (int mf = 0; mf < 2; mf++)
            #pragma unroll
            for (int j = 0; j < 8; j++) {
                int c = nh4 * 64 + j * 8 + tq;
                int ai = (mf * 8 + j) * 4;
                float pg0 = post_g[c], pg1 = post_g[c + 1];
                float pbb0 = post_b[c], pbb1 = post_b[c + 1];
                int rlo = mf * 2, rhi = mf * 2 + 1;
                float t00 = acc[ai + 0], t01 = acc[ai + 1];
                float t10 = acc[ai + 2], t11 = acc[ai + 3];
                Ob[(size_t)c * 65536 + xo[rlo]]       = t00 + (t00 - mm[rlo]) * ii[rlo] * pg0 + pbb0;
                Ob[(size_t)(c + 1) * 65536 + xo[rlo]] = t01 + (t01 - mm[rlo]) * ii[rlo] * pg1 + pbb1;
                Ob[(size_t)c * 65536 + xo[rhi]]       = t10 + (t10 - mm[rhi]) * ii[rhi] * pg0 + pbb0;
                Ob[(size_t)(c + 1) * 65536 + xo[rhi]] = t11 + (t11 - mm[rhi]) * ii[rhi] * pg1 + pbb1;
            }
    }
}

extern "C" void kernel_launch(void* const* d_in, const int* in_sizes, int n_in,
                              void* d_out, int out_size) {
    const float* X      = (const float*)d_in[0];
    const float* pre_g  = (const float*)d_in[1];
    const float* pre_b  = (const float*)d_in[2];
    const float* post_g = (const float*)d_in[3];
    const float* post_b = (const float*)d_in[4];
    const float* qkv_w  = (const float*)d_in[5];
    const float* qkv_b  = (const float*)d_in[6];
    const float* proj_w = (const float*)d_in[7];
    const float* proj_b = (const float*)d_in[8];
    const float* rtab   = (const float*)d_in[9];
    const int*   ridx   = (const int*)d_in[10];
    float* out = (float*)d_out;

    const int smem_bytes = SMEM_FLOATS * 4;   // 103,936 B -> 2 CTAs/SM
    cudaFuncSetAttribute(window_attn_kernel,
                         cudaFuncAttributeMaxDynamicSharedMemorySize, smem_bytes);

    prep_bias<<<256, 256>>>(rtab, ridx);
    prep_wq<<<768, 256>>>(qkv_w);
    prep_wp<<<256, 256>>>(proj_w);
    window_attn_kernel<<<2048, 256, smem_bytes>>>(
        X, pre_g, pre_b, post_g, post_b, qkv_b, proj_b, out);
}

// round 10
// speedup vs baseline: 24.1014x; 1.1351x over previous
#include <cuda_runtime.h>
#include <cuda_bf16.h>
#include <cstdint>

#define HEADS 16
#define NW 64
#define CH 256
#define PA 264      // pitch (halves) bf16 activation buffers [64 x 256]
#define PQK 24      // pitch (halves) q/k head tiles [64 x 16]
#define PVT 72      // pitch (halves) vT head tiles [16 x 64]

// smem float offsets
#define OFF_AN 0        // s_an: bf16 [64][264] = 8448 fl
#define OFF_AB 8448     // s_ab: bf16 [64][264] = 8448 fl
#define OFF_R  16896    // tiles: q 6144h + k 6144h + vT 4608h = 16896h = 8448 fl
#define OFF_MI 25344    // s_m[64], s_i[64]
#define OFF_RED 25472   // s_red float2[64][4] = 512 fl
#define SMEM_FLOATS 25984

__device__ __nv_bfloat16 g_biasb[HEADS * NW * NW];
__device__ uint2 g_wqf[4 * 8 * 2 * 4 * 6 * 32];   // [p][kb][ks][nh4][j][lane] B-fragments
__device__ uint2 g_wpf[16 * 4 * 8 * 32];          // [kb][nh4][j][lane] B-fragments

__global__ void prep_bias(const float* __restrict__ table,
                          const int* __restrict__ ridx) {
    int t = blockIdx.x * blockDim.x + threadIdx.x;
    if (t < HEADS * NW * NW) {
        int h = t >> 12;
        int ij = t & 4095;
        g_biasb[t] = __float2bfloat16(table[ridx[ij] * HEADS + h]);
    }
}
__device__ __forceinline__ uint32_t pk2(float lo, float hi) {
    __nv_bfloat162 h = __floats2bfloat162_rn(lo, hi);
    return *(uint32_t*)&h;
}
__global__ void prep_wq_frag(const float* __restrict__ qkv_w) {
    int t = blockIdx.x * blockDim.x + threadIdx.x;
    if (t >= 49152) return;
    int lane = t & 31;
    int r = t >> 5;
    int j = r % 6; r /= 6;
    int nh4 = r & 3; r >>= 2;
    int ks = r & 1; r >>= 1;
    int kb = r & 7; r >>= 3;
    int p = r;
    int g = lane >> 2, tq = (lane & 3) * 2;
    int n = nh4 * 48 + j * 8 + g;
    int gcol = (n >> 6) * 256 + p * 64 + (n & 63);
    int k0 = kb * 32 + ks * 16 + tq;
    uint2 v;
    v.x = pk2(qkv_w[(size_t)k0 * 768 + gcol],       qkv_w[(size_t)(k0 + 1) * 768 + gcol]);
    v.y = pk2(qkv_w[(size_t)(k0 + 8) * 768 + gcol], qkv_w[(size_t)(k0 + 9) * 768 + gcol]);
    g_wqf[t] = v;
}
__global__ void prep_wp_frag(const float* __restrict__ proj_w) {
    int t = blockIdx.x * blockDim.x + threadIdx.x;
    if (t >= 16384) return;
    int lane = t & 31;
    int r = t >> 5;
    int j = r & 7; r >>= 3;
    int nh4 = r & 3; r >>= 2;
    int kb = r;
    int g = lane >> 2, tq = (lane & 3) * 2;
    int n = nh4 * 64 + j * 8 + g;
    int k0 = kb * 16 + tq;
    uint2 v;
    v.x = pk2(proj_w[(size_t)k0 * 256 + n],       proj_w[(size_t)(k0 + 1) * 256 + n]);
    v.y = pk2(proj_w[(size_t)(k0 + 8) * 256 + n], proj_w[(size_t)(k0 + 9) * 256 + n]);
    g_wpf[t] = v;
}

__device__ __forceinline__ uint32_t SAu(const void* p) {
    return (uint32_t)__cvta_generic_to_shared(p);
}
__device__ __forceinline__ void ldsm4(uint32_t* r, uint32_t a) {
    asm volatile("ldmatrix.sync.aligned.m8n8.x4.shared.b16 {%0,%1,%2,%3}, [%4];"
        : "=r"(r[0]), "=r"(r[1]), "=r"(r[2]), "=r"(r[3]) : "r"(a));
}
__device__ __forceinline__ void stsm4(uint32_t a, uint32_t r0, uint32_t r1,
                                      uint32_t r2, uint32_t r3) {
    asm volatile("stmatrix.sync.aligned.m8n8.x4.shared.b16 [%0], {%1,%2,%3,%4};"
        :: "r"(a), "r"(r0), "r"(r1), "r"(r2), "r"(r3) : "memory");
}
__device__ __forceinline__ void mma16816(float* c, uint32_t a0, uint32_t a1,
                                         uint32_t a2, uint32_t a3,
                                         uint32_t b0, uint32_t b1) {
    asm volatile("mma.sync.aligned.m16n8k16.row.col.f32.bf16.bf16.f32 "
        "{%0,%1,%2,%3}, {%4,%5,%6,%7}, {%8,%9}, {%0,%1,%2,%3};"
        : "+f"(c[0]), "+f"(c[1]), "+f"(c[2]), "+f"(c[3])
        : "r"(a0), "r"(a1), "r"(a2), "r"(a3), "r"(b0), "r"(b1));
}
__device__ __forceinline__ uint32_t pack2(float lo, float hi) {
    __nv_bfloat162 h = __floats2bfloat162_rn(lo, hi);
    return *(uint32_t*)&h;
}
__device__ __forceinline__ float2 unpack2(uint32_t u) {
    __nv_bfloat162 h = *(__nv_bfloat162*)&u;
    return make_float2(__bfloat162float(h.x), __bfloat162float(h.y));
}
__device__ __forceinline__ uint16_t bfr(float v) {
    __nv_bfloat16 h = __float2bfloat16(v);
    return *(uint16_t*)&h;
}

__global__ __launch_bounds__(256, 2)
void window_attn_kernel(const float* __restrict__ X,
                        const float* __restrict__ pre_g, const float* __restrict__ pre_b,
                        const float* __restrict__ post_g, const float* __restrict__ post_b,
                        const float* __restrict__ qkv_b, const float* __restrict__ proj_b,
                        float* __restrict__ out) {
    extern __shared__ float sm[];
    uint16_t*  s_an = (uint16_t*)(sm + OFF_AN);
    uint16_t*  s_ab = (uint16_t*)(sm + OFF_AB);
    uint16_t*  s_R  = (uint16_t*)(sm + OFF_R);
    uint16_t*  s_qt = s_R;                 // [4][64][24]
    uint16_t*  s_kt = s_R + 6144;          // [4][64][24]
    uint16_t*  s_vt = s_R + 12288;         // [4][16][72]
    float*     s_m  = sm + OFF_MI;
    float*     s_i  = sm + OFF_MI + 64;
    float2 (*s_red)[4] = (float2(*)[4])(sm + OFF_RED);

    const uint32_t an_b = SAu(s_an);
    const uint32_t ab_b = SAu(s_ab);
    const uint32_t qt_b = SAu(s_qt);
    const uint32_t kt_b = SAu(s_kt);
    const uint32_t vt_b = SAu(s_vt);

    const int w    = blockIdx.x;
    const int b    = w >> 10;
    const int hi   = (w >> 5) & 31;
    const int wi   = w & 31;
    const int tid  = threadIdx.x;
    const int lane = tid & 31;
    const int warp = tid >> 5;

    const float* Xb = X + (size_t)b * (CH * 65536) + hi * 8 * 256 + wi * 8;
    float*       Ob = out + (size_t)b * (CH * 65536) + hi * 8 * 256 + wi * 8;

    // ---------- phase 0: pre-LN from global, X kept in registers ----------
    {
        const int n0 = tid >> 2;
        const int cb = tid & 3;
        float v[64];
        float s = 0.f, s2 = 0.f;
        const float* Xt = Xb + (n0 >> 3) * 256 + (n0 & 7);
        #pragma unroll
        for (int i = 0; i < 64; i++) {
            v[i] = Xt[(size_t)(cb + 4 * i) * 65536];
            s += v[i]; s2 += v[i] * v[i];
        }
        s  += __shfl_xor_sync(0xffffffffu, s, 1);
        s  += __shfl_xor_sync(0xffffffffu, s, 2);
        s2 += __shfl_xor_sync(0xffffffffu, s2, 1);
        s2 += __shfl_xor_sync(0xffffffffu, s2, 2);
        float mean = s * (1.f / 256.f);
        float inv  = rsqrtf(s2 * (1.f / 256.f) - mean * mean + 1e-5f);
        #pragma unroll
        for (int i = 0; i < 64; i++) {
            int c = cb + 4 * i;
            float y = (v[i] - mean) * inv * pre_g[c] + pre_b[c];
            s_an[n0 * PA + c] = bfr(y);
        }
    }
    __syncthreads();

    // mma thread mapping
    const int g      = lane >> 2;
    const int tq     = (lane & 3) * 2;
    const int lane15 = lane & 15;
    const int lhi8   = (lane & 16) ? 8 : 0;
    const int brow   = (lane & 7) + lhi8;
    const int bk     = (lane & 8) ? 8 : 0;
    const int m0     = (warp & 1) * 32;     // 2-way m split
    const int nh4    = warp >> 1;           // 4-way n split

    // ---------- phase 2: 4 passes of (qkv HMMA -> reg epilogue -> HMMA attention) ----------
    #pragma unroll 1
    for (int p = 0; p < 4; p++) {
        float acc[48];
        #pragma unroll
        for (int i = 0; i < 48; i++) acc[i] = 0.f;

        // B fragments straight from L2 (fragment-layout global); no smem, no syncs
        const uint2* gwf = g_wqf + p * 12288 + lane;

        #pragma unroll 1
        for (int kb = 0; kb < 8; kb++) {
            uint2 Bf[12];
            #pragma unroll
            for (int ks = 0; ks < 2; ks++)
                #pragma unroll
                for (int j = 0; j < 6; j++)
                    Bf[ks * 6 + j] = __ldg(gwf + (((kb * 2 + ks) * 4 + nh4) * 6 + j) * 32);
            #pragma unroll
            for (int ks = 0; ks < 2; ks++) {
                uint32_t Af[2][4];
                #pragma unroll
                for (int mf = 0; mf < 2; mf++)
                    ldsm4(Af[mf], an_b +
                        (((m0 + mf * 16 + lane15) * PA + kb * 32 + ks * 16 + lhi8) << 1));
                #pragma unroll
                for (int mf = 0; mf < 2; mf++)
                    #pragma unroll
                    for (int j = 0; j < 6; j++)
                        mma16816(&acc[(mf * 6 + j) * 4],
                                 Af[mf][0], Af[mf][1], Af[mf][2], Af[mf][3],
                                 Bf[ks * 6 + j].x, Bf[ks * 6 + j].y);
            }
        }

        // ---- register epilogue: bias + l2norm (quad shuffles) -> bf16 tiles ----
        #pragma unroll
        for (int bi = 0; bi < 3; bi++) {
            const int blk = nh4 * 3 + bi;   // 0..3 q heads, 4..7 k heads, 8..11 v heads
            const int jj0 = bi * 2;
            #pragma unroll
            for (int mf = 0; mf < 2; mf++) {
                float tv[2][4];
                #pragma unroll
                for (int jj = 0; jj < 2; jj++) {
                    int nl = nh4 * 48 + (jj0 + jj) * 8 + tq;
                    int gcol = (nl >> 6) * 256 + p * 64 + (nl & 63);
                    float b0 = qkv_b[gcol], b1 = qkv_b[gcol + 1];
                    int ai = (mf * 6 + jj0 + jj) * 4;
                    tv[jj][0] = acc[ai + 0] + b0;
                    tv[jj][1] = acc[ai + 1] + b1;
                    tv[jj][2] = acc[ai + 2] + b0;
                    tv[jj][3] = acc[ai + 3] + b1;
                }
                if (blk < 8) {
                    float s0 = tv[0][0]*tv[0][0] + tv[0][1]*tv[0][1]
                             + tv[1][0]*tv[1][0] + tv[1][1]*tv[1][1];
                    float s1 = tv[0][2]*tv[0][2] + tv[0][3]*tv[0][3]
                             + tv[1][2]*tv[1][2] + tv[1][3]*tv[1][3];
                    s0 += __shfl_xor_sync(0xffffffffu, s0, 1);
                    s0 += __shfl_xor_sync(0xffffffffu, s0, 2);
                    s1 += __shfl_xor_sync(0xffffffffu, s1, 1);
                    s1 += __shfl_xor_sync(0xffffffffu, s1, 2);
                    float r0s = 1.f / fmaxf(sqrtf(s0), 1e-12f);
                    float r1s = 1.f / fmaxf(sqrtf(s1), 1e-12f);
                    int head = blk & 3;
                    uint32_t base = (blk < 4) ? qt_b : kt_b;
                    stsm4(base + (((head * 64 + m0 + mf * 16 + lane15) * PQK + lhi8) << 1),
                          pack2(tv[0][0] * r0s, tv[0][1] * r0s),
                          pack2(tv[0][2] * r1s, tv[0][3] * r1s),
                          pack2(tv[1][0] * r0s, tv[1][1] * r0s),
                          pack2(tv[1][2] * r1s, tv[1][3] * r1s));
                } else {
                    int hv = blk - 8;
                    int rl = m0 + mf * 16 + g, rh = rl + 8;
                    #pragma unroll
                    for (int jj = 0; jj < 2; jj++) {
                        int dv = jj * 8 + tq;
                        uint16_t* vp = s_vt + (hv * 16 + dv) * PVT;
                        vp[rl]       = bfr(tv[jj][0]);
                        vp[PVT + rl] = bfr(tv[jj][1]);
                        vp[rh]       = bfr(tv[jj][2]);
                        vp[PVT + rh] = bfr(tv[jj][3]);
                    }
                }
            }
        }
        __syncthreads();

        // ---- HMMA attention: warp -> (head wh, row-half mh) ----
        {
            const int wh = warp >> 1, mh = warp & 1;
            const uint32_t* gb = (const uint32_t*)g_biasb + (p * 4 + wh) * 2048;

            uint32_t kb0[8], kb1[8];
            #pragma unroll
            for (int jp = 0; jp < 4; jp++) {
                uint32_t r[4];
                ldsm4(r, kt_b + (((wh * 64 + jp * 16 + brow) * PQK + bk) << 1));
                kb0[2 * jp] = r[0]; kb1[2 * jp] = r[1];
                kb0[2 * jp + 1] = r[2]; kb1[2 * jp + 1] = r[3];
            }
            uint32_t vb0[4][2], vb1[4][2];
            #pragma unroll
            for (int ks = 0; ks < 4; ks++) {
                uint32_t r[4];
                ldsm4(r, vt_b + (((wh * 16 + brow) * PVT + ks * 16 + bk) << 1));
                vb0[ks][0] = r[0]; vb1[ks][0] = r[1];
                vb0[ks][1] = r[2]; vb1[ks][1] = r[3];
            }

            #pragma unroll
            for (int t = 0; t < 2; t++) {
                int r = mh * 32 + t * 16;
                uint32_t qa[4];
                ldsm4(qa, qt_b + (((wh * 64 + r + lane15) * PQK + lhi8) << 1));

                float Sc[8][4];
                #pragma unroll
                for (int j = 0; j < 8; j++) {
                    float2 f0 = unpack2(gb[(r + g) * 32 + j * 4 + (tq >> 1)]);
                    float2 f1 = unpack2(gb[(r + g + 8) * 32 + j * 4 + (tq >> 1)]);
                    Sc[j][0] = f0.x; Sc[j][1] = f0.y;
                    Sc[j][2] = f1.x; Sc[j][3] = f1.y;
                }
                #pragma unroll
                for (int j = 0; j < 8; j++)
                    mma16816(Sc[j], qa[0], qa[1], qa[2], qa[3], kb0[j], kb1[j]);

                float su0 = 0.f, su1 = 0.f;
                #pragma unroll
                for (int j = 0; j < 8; j++) {
                    Sc[j][0] = __expf(Sc[j][0]);
                    Sc[j][1] = __expf(Sc[j][1]);
                    Sc[j][2] = __expf(Sc[j][2]);
                    Sc[j][3] = __expf(Sc[j][3]);
                    su0 += Sc[j][0] + Sc[j][1];
                    su1 += Sc[j][2] + Sc[j][3];
                }
                su0 += __shfl_xor_sync(0xffffffffu, su0, 1);
                su0 += __shfl_xor_sync(0xffffffffu, su0, 2);
                su1 += __shfl_xor_sync(0xffffffffu, su1, 1);
                su1 += __shfl_xor_sync(0xffffffffu, su1, 2);
                float inv0 = 1.f / su0, inv1 = 1.f / su1;

                float Oc[2][4];
                #pragma unroll
                for (int nt = 0; nt < 2; nt++)
                    #pragma unroll
                    for (int i = 0; i < 4; i++) Oc[nt][i] = 0.f;

                #pragma unroll
                for (int ks = 0; ks < 4; ks++) {
                    uint32_t pa0 = pack2(Sc[2 * ks][0] * inv0,     Sc[2 * ks][1] * inv0);
                    uint32_t pa1 = pack2(Sc[2 * ks][2] * inv1,     Sc[2 * ks][3] * inv1);
                    uint32_t pa2 = pack2(Sc[2 * ks + 1][0] * inv0, Sc[2 * ks + 1][1] * inv0);
                    uint32_t pa3 = pack2(Sc[2 * ks + 1][2] * inv1, Sc[2 * ks + 1][3] * inv1);
                    #pragma unroll
                    for (int nt = 0; nt < 2; nt++)
                        mma16816(Oc[nt], pa0, pa1, pa2, pa3, vb0[ks][nt], vb1[ks][nt]);
                }

                int hc = (p * 4 + wh) * 16;
                stsm4(ab_b + (((r + lane15) * PA + hc + lhi8) << 1),
                      pack2(Oc[0][0], Oc[0][1]), pack2(Oc[0][2], Oc[0][3]),
                      pack2(Oc[1][0], Oc[1][1]), pack2(Oc[1][2], Oc[1][3]));
            }
        }
        __syncthreads();
    }

    // ---------- phase 3: proj HMMA (B fragments from L2, zero-sync mainloop) ----------
    float acc[64];
    #pragma unroll
    for (int i = 0; i < 64; i++) acc[i] = 0.f;

    #pragma unroll 1
    for (int kb = 0; kb < 16; kb++) {
        uint2 Bf[8];
        #pragma unroll
        for (int j = 0; j < 8; j++)
            Bf[j] = __ldg(g_wpf + ((kb * 4 + nh4) * 8 + j) * 32 + lane);
        uint32_t Af[2][4];
        #pragma unroll
        for (int mf = 0; mf < 2; mf++)
            ldsm4(Af[mf], ab_b + (((m0 + mf * 16 + lane15) * PA + kb * 16 + lhi8) << 1));
        #pragma unroll
        for (int mf = 0; mf < 2; mf++)
            #pragma unroll
            for (int j = 0; j < 8; j++)
                mma16816(&acc[(mf * 8 + j) * 4],
                         Af[mf][0], Af[mf][1], Af[mf][2], Af[mf][3],
                         Bf[j].x, Bf[j].y);
    }

    // ---------- phase 4: t = proj + bias + x (regs); post-LN; scatter out ----------
    {
        int rows[4], xo[4];
        #pragma unroll
        for (int mf = 0; mf < 2; mf++) {
            rows[mf * 2 + 0] = m0 + mf * 16 + g;
            rows[mf * 2 + 1] = m0 + mf * 16 + g + 8;
        }
        #pragma unroll
        for (int i = 0; i < 4; i++) xo[i] = (rows[i] >> 3) * 256 + (rows[i] & 7);

        float rs[4], rs2[4];
        #pragma unroll
        for (int i = 0; i < 4; i++) { rs[i] = 0.f; rs2[i] = 0.f; }

        #pragma unroll
        for (int mf = 0; mf < 2; mf++)
            #pragma unroll
            for (int j = 0; j < 8; j++) {
                int c = nh4 * 64 + j * 8 + tq;
                int ai = (mf * 8 + j) * 4;
                float pb0 = proj_b[c], pb1 = proj_b[c + 1];
                acc[ai + 0] += pb0 + Xb[(size_t)c * 65536 + xo[mf * 2]];
                acc[ai + 1] += pb1 + Xb[(size_t)(c + 1) * 65536 + xo[mf * 2]];
                acc[ai + 2] += pb0 + Xb[(size_t)c * 65536 + xo[mf * 2 + 1]];
                acc[ai + 3] += pb1 + Xb[(size_t)(c + 1) * 65536 + xo[mf * 2 + 1]];
                rs[mf * 2]      += acc[ai + 0] + acc[ai + 1];
                rs2[mf * 2]     += acc[ai + 0] * acc[ai + 0] + acc[ai + 1] * acc[ai + 1];
                rs[mf * 2 + 1]  += acc[ai + 2] + acc[ai + 3];
                rs2[mf * 2 + 1] += acc[ai + 2] * acc[ai + 2] + acc[ai + 3] * acc[ai + 3];
            }
        #pragma unroll
        for (int i = 0; i < 4; i++) {
            rs[i]  += __shfl_xor_sync(0xffffffffu, rs[i], 1);
            rs[i]  += __shfl_xor_sync(0xffffffffu, rs[i], 2);
            rs2[i] += __shfl_xor_sync(0xffffffffu, rs2[i], 1);
            rs2[i] += __shfl_xor_sync(0xffffffffu, rs2[i], 2);
        }
        if (tq == 0) {
            #pragma unroll
            for (int i = 0; i < 4; i++)
                s_red[rows[i]][nh4] = make_float2(rs[i], rs2[i]);
        }
        __syncthreads();
        if (tid < 64) {
            float ts = 0.f, ts2 = 0.f;
            #pragma unroll
            for (int q4 = 0; q4 < 4; q4++) {
                float2 a = s_red[tid][q4];
                ts += a.x; ts2 += a.y;
            }
            float mean = ts * (1.f / 256.f);
            s_m[tid] = mean;
            s_i[tid] = rsqrtf(ts2 * (1.f / 256.f) - mean * mean + 1e-5f);
        }
        __syncthreads();

        float mm[4], ii[4];
        #pragma unroll
        for (int i = 0; i < 4; i++) { mm[i] = s_m[rows[i]]; ii[i] = s_i[rows[i]]; }

        #pragma unroll
        for (int mf = 0; mf < 2; mf++)
            #pragma unroll
            for (int j = 0; j < 8; j++) {
                int c = nh4 * 64 + j * 8 + tq;
                int ai = (mf * 8 + j) * 4;
                float pg0 = post_g[c], pg1 = post_g[c + 1];
                float pbb0 = post_b[c], pbb1 = post_b[c + 1];
                int rlo = mf * 2, rhi = mf * 2 + 1;
                float t00 = acc[ai + 0], t01 = acc[ai + 1];
                float t10 = acc[ai + 2], t11 = acc[ai + 3];
                Ob[(size_t)c * 65536 + xo[rlo]]       = t00 + (t00 - mm[rlo]) * ii[rlo] * pg0 + pbb0;
                Ob[(size_t)(c + 1) * 65536 + xo[rlo]] = t01 + (t01 - mm[rlo]) * ii[rlo] * pg1 + pbb1;
                Ob[(size_t)c * 65536 + xo[rhi]]       = t10 + (t10 - mm[rhi]) * ii[rhi] * pg0 + pbb0;
                Ob[(size_t)(c + 1) * 65536 + xo[rhi]] = t11 + (t11 - mm[rhi]) * ii[rhi] * pg1 + pbb1;
            }
    }
}

extern "C" void kernel_launch(void* const* d_in, const int* in_sizes, int n_in,
                              void* d_out, int out_size) {
    const float* X      = (const float*)d_in[0];
    const float* pre_g  = (const float*)d_in[1];
    const float* pre_b  = (const float*)d_in[2];
    const float* post_g = (const float*)d_in[3];
    const float* post_b = (const float*)d_in[4];
    const float* qkv_w  = (const float*)d_in[5];
    const float* qkv_b  = (const float*)d_in[6];
    const float* proj_w = (const float*)d_in[7];
    const float* proj_b = (const float*)d_in[8];
    const float* rtab   = (const float*)d_in[9];
    const int*   ridx   = (const int*)d_in[10];
    float* out = (float*)d_out;

    const int smem_bytes = SMEM_FLOATS * 4;   // 103,936 B -> 2 CTAs/SM
    cudaFuncSetAttribute(window_attn_kernel,
                         cudaFuncAttributeMaxDynamicSharedMemorySize, smem_bytes);

    prep_bias<<<256, 256>>>(rtab, ridx);
    prep_wq_frag<<<192, 256>>>(qkv_w);
    prep_wp_frag<<<64, 256>>>(proj_w);
    window_attn_kernel<<<2048, 256, smem_bytes>>>(
        X, pre_g, pre_b, post_g, post_b, qkv_b, proj_b, out);
}

// round 12
// speedup vs baseline: 28.4272x; 1.1795x over previous
#include <cuda_runtime.h>
#include <cuda_bf16.h>
#include <cstdint>

#define HEADS 16
#define NW 64
#define CH 256
#define PA 264      // pitch (halves) bf16 activation buffers [64 x 256]
#define PQK 24      // pitch (halves) q/k head tiles [64 x 16]
#define PVT 72      // pitch (halves) vT head tiles [16 x 64]

// smem float offsets
#define OFF_AN 0        // s_an: bf16 [64][264] = 8448 fl
#define OFF_AB 8448     // s_ab: bf16 [64][264] = 8448 fl
#define OFF_R  16896    // tiles: q 6144h + k 6144h + vT 4608h = 16896h = 8448 fl
#define OFF_MI 25344    // s_m[64], s_i[64]
#define OFF_RED 25472   // s_red float2[64][4] = 512 fl
#define SMEM_FLOATS 25984

__device__ uint2 g_biasf[HEADS * 4 * 8 * 32];     // [h][rowtile(4)][j(8)][lane] C-fragment bias
__device__ uint2 g_wqf[4 * 8 * 2 * 4 * 6 * 32];   // [p][kb][ks][nh4][j][lane] B-fragments
__device__ uint2 g_wpf[16 * 4 * 8 * 32];          // [kb][nh4][j][lane] B-fragments

__device__ __forceinline__ uint32_t pk2(float lo, float hi) {
    __nv_bfloat162 h = __floats2bfloat162_rn(lo, hi);
    return *(uint32_t*)&h;
}
__global__ void prep_bias_frag(const float* __restrict__ table,
                               const int* __restrict__ ridx) {
    int t = blockIdx.x * blockDim.x + threadIdx.x;
    if (t >= 16384) return;
    int lane = t & 31;
    int r = t >> 5;
    int j = r & 7; r >>= 3;
    int rt = r & 3; r >>= 2;
    int h = r;
    int g = lane >> 2, tq = (lane & 3) * 2;
    int row0 = rt * 16 + g, row1 = row0 + 8, col = j * 8 + tq;
    float b00 = table[ridx[row0 * 64 + col] * HEADS + h];
    float b01 = table[ridx[row0 * 64 + col + 1] * HEADS + h];
    float b10 = table[ridx[row1 * 64 + col] * HEADS + h];
    float b11 = table[ridx[row1 * 64 + col + 1] * HEADS + h];
    uint2 v;
    v.x = pk2(b00, b01);
    v.y = pk2(b10, b11);
    g_biasf[t] = v;
}
__global__ void prep_wq_frag(const float* __restrict__ qkv_w) {
    int t = blockIdx.x * blockDim.x + threadIdx.x;
    if (t >= 49152) return;
    int lane = t & 31;
    int r = t >> 5;
    int j = r % 6; r /= 6;
    int nh4 = r & 3; r >>= 2;
    int ks = r & 1; r >>= 1;
    int kb = r & 7; r >>= 3;
    int p = r;
    int g = lane >> 2, tq = (lane & 3) * 2;
    int n = nh4 * 48 + j * 8 + g;
    int gcol = (n >> 6) * 256 + p * 64 + (n & 63);
    int k0 = kb * 32 + ks * 16 + tq;
    uint2 v;
    v.x = pk2(qkv_w[(size_t)k0 * 768 + gcol],       qkv_w[(size_t)(k0 + 1) * 768 + gcol]);
    v.y = pk2(qkv_w[(size_t)(k0 + 8) * 768 + gcol], qkv_w[(size_t)(k0 + 9) * 768 + gcol]);
    g_wqf[t] = v;
}
__global__ void prep_wp_frag(const float* __restrict__ proj_w) {
    int t = blockIdx.x * blockDim.x + threadIdx.x;
    if (t >= 16384) return;
    int lane = t & 31;
    int r = t >> 5;
    int j = r & 7; r >>= 3;
    int nh4 = r & 3; r >>= 2;
    int kb = r;
    int g = lane >> 2, tq = (lane & 3) * 2;
    int n = nh4 * 64 + j * 8 + g;
    int k0 = kb * 16 + tq;
    uint2 v;
    v.x = pk2(proj_w[(size_t)k0 * 256 + n],       proj_w[(size_t)(k0 + 1) * 256 + n]);
    v.y = pk2(proj_w[(size_t)(k0 + 8) * 256 + n], proj_w[(size_t)(k0 + 9) * 256 + n]);
    g_wpf[t] = v;
}

__device__ __forceinline__ uint32_t SAu(const void* p) {
    return (uint32_t)__cvta_generic_to_shared(p);
}
__device__ __forceinline__ void ldsm4(uint32_t* r, uint32_t a) {
    asm volatile("ldmatrix.sync.aligned.m8n8.x4.shared.b16 {%0,%1,%2,%3}, [%4];"
        : "=r"(r[0]), "=r"(r[1]), "=r"(r[2]), "=r"(r[3]) : "r"(a));
}
__device__ __forceinline__ void stsm4(uint32_t a, uint32_t r0, uint32_t r1,
                                      uint32_t r2, uint32_t r3) {
    asm volatile("stmatrix.sync.aligned.m8n8.x4.shared.b16 [%0], {%1,%2,%3,%4};"
        :: "r"(a), "r"(r0), "r"(r1), "r"(r2), "r"(r3) : "memory");
}
__device__ __forceinline__ void mma16816(float* c, uint32_t a0, uint32_t a1,
                                         uint32_t a2, uint32_t a3,
                                         uint32_t b0, uint32_t b1) {
    asm volatile("mma.sync.aligned.m16n8k16.row.col.f32.bf16.bf16.f32 "
        "{%0,%1,%2,%3}, {%4,%5,%6,%7}, {%8,%9}, {%0,%1,%2,%3};"
        : "+f"(c[0]), "+f"(c[1]), "+f"(c[2]), "+f"(c[3])
        : "r"(a0), "r"(a1), "r"(a2), "r"(a3), "r"(b0), "r"(b1));
}
__device__ __forceinline__ uint32_t pack2(float lo, float hi) {
    __nv_bfloat162 h = __floats2bfloat162_rn(lo, hi);
    return *(uint32_t*)&h;
}
__device__ __forceinline__ float2 unpack2(uint32_t u) {
    __nv_bfloat162 h = *(__nv_bfloat162*)&u;
    return make_float2(__bfloat162float(h.x), __bfloat162float(h.y));
}
__device__ __forceinline__ uint16_t bfr(float v) {
    __nv_bfloat16 h = __float2bfloat16(v);
    return *(uint16_t*)&h;
}

__global__ __launch_bounds__(256, 2)
void window_attn_kernel(const float* __restrict__ X,
                        const float* __restrict__ pre_g, const float* __restrict__ pre_b,
                        const float* __restrict__ post_g, const float* __restrict__ post_b,
                        const float* __restrict__ qkv_b, const float* __restrict__ proj_b,
                        float* __restrict__ out) {
    extern __shared__ float sm[];
    uint16_t*  s_an = (uint16_t*)(sm + OFF_AN);
    uint16_t*  s_ab = (uint16_t*)(sm + OFF_AB);
    uint16_t*  s_R  = (uint16_t*)(sm + OFF_R);
    uint16_t*  s_qt = s_R;                 // [4][64][24]
    uint16_t*  s_kt = s_R + 6144;          // [4][64][24]
    uint16_t*  s_vt = s_R + 12288;         // [4][16][72]
    float*     s_m  = sm + OFF_MI;
    float*     s_i  = sm + OFF_MI + 64;
    float2 (*s_red)[4] = (float2(*)[4])(sm + OFF_RED);

    const uint32_t an_b = SAu(s_an);
    const uint32_t ab_b = SAu(s_ab);
    const uint32_t qt_b = SAu(s_qt);
    const uint32_t kt_b = SAu(s_kt);
    const uint32_t vt_b = SAu(s_vt);

    const int w    = blockIdx.x;
    const int b    = w >> 10;
    const int hi   = (w >> 5) & 31;
    const int wi   = w & 31;
    const int tid  = threadIdx.x;
    const int lane = tid & 31;
    const int warp = tid >> 5;

    const float* Xb = X + (size_t)b * (CH * 65536) + hi * 8 * 256 + wi * 8;
    float*       Ob = out + (size_t)b * (CH * 65536) + hi * 8 * 256 + wi * 8;

    // ---------- phase 0: pre-LN from global, X kept in registers ----------
    {
        const int n0 = tid >> 2;
        const int cb = tid & 3;
        float v[64];
        float s = 0.f, s2 = 0.f;
        const float* Xt = Xb + (n0 >> 3) * 256 + (n0 & 7);
        #pragma unroll
        for (int i = 0; i < 64; i++) {
            v[i] = Xt[(size_t)(cb + 4 * i) * 65536];
            s += v[i]; s2 += v[i] * v[i];
        }
        s  += __shfl_xor_sync(0xffffffffu, s, 1);
        s  += __shfl_xor_sync(0xffffffffu, s, 2);
        s2 += __shfl_xor_sync(0xffffffffu, s2, 1);
        s2 += __shfl_xor_sync(0xffffffffu, s2, 2);
        float mean = s * (1.f / 256.f);
        float inv  = rsqrtf(s2 * (1.f / 256.f) - mean * mean + 1e-5f);
        #pragma unroll
        for (int i = 0; i < 64; i++) {
            int c = cb + 4 * i;
            float y = (v[i] - mean) * inv * pre_g[c] + pre_b[c];
            s_an[n0 * PA + c] = bfr(y);
        }
    }
    __syncthreads();

    // mma thread mapping
    const int g      = lane >> 2;
    const int tq     = (lane & 3) * 2;
    const int lane15 = lane & 15;
    const int lhi8   = (lane & 16) ? 8 : 0;
    const int brow   = (lane & 7) + lhi8;
    const int bk     = (lane & 8) ? 8 : 0;
    const int m0     = (warp & 1) * 32;     // 2-way m split
    const int nh4    = warp >> 1;           // 4-way n split

    // ---------- phase 2: 4 passes of (qkv HMMA -> reg epilogue -> HMMA attention) ----------
    #pragma unroll 1
    for (int p = 0; p < 4; p++) {
        float acc[48];
        #pragma unroll
        for (int i = 0; i < 48; i++) acc[i] = 0.f;

        // pipelined B fragments from L2 (fragment-layout global)
        const uint2* gwf = g_wqf + p * 12288 + lane;

        uint2 Ba[6], Bb[6];
        #pragma unroll
        for (int j = 0; j < 6; j++)
            Ba[j] = __ldg(gwf + ((0 * 4 + nh4) * 6 + j) * 32);

        #pragma unroll 1
        for (int kb = 0; kb < 8; kb++) {
            // issue ks=1 fetch before ks=0 MMAs
            #pragma unroll
            for (int j = 0; j < 6; j++)
                Bb[j] = __ldg(gwf + (((kb * 2 + 1) * 4 + nh4) * 6 + j) * 32);

            uint32_t Af[2][4];
            #pragma unroll
            for (int mf = 0; mf < 2; mf++)
                ldsm4(Af[mf], an_b +
                    (((m0 + mf * 16 + lane15) * PA + kb * 32 + lhi8) << 1));
            #pragma unroll
            for (int mf = 0; mf < 2; mf++)
                #pragma unroll
                for (int j = 0; j < 6; j++)
                    mma16816(&acc[(mf * 6 + j) * 4],
                             Af[mf][0], Af[mf][1], Af[mf][2], Af[mf][3],
                             Ba[j].x, Ba[j].y);

            // issue next kb ks=0 fetch before ks=1 MMAs
            if (kb < 7) {
                #pragma unroll
                for (int j = 0; j < 6; j++)
                    Ba[j] = __ldg(gwf + ((((kb + 1) * 2) * 4 + nh4) * 6 + j) * 32);
            }
            #pragma unroll
            for (int mf = 0; mf < 2; mf++)
                ldsm4(Af[mf], an_b +
                    (((m0 + mf * 16 + lane15) * PA + kb * 32 + 16 + lhi8) << 1));
            #pragma unroll
            for (int mf = 0; mf < 2; mf++)
                #pragma unroll
                for (int j = 0; j < 6; j++)
                    mma16816(&acc[(mf * 6 + j) * 4],
                             Af[mf][0], Af[mf][1], Af[mf][2], Af[mf][3],
                             Bb[j].x, Bb[j].y);
        }

        // ---- register epilogue: bias + l2norm (quad shuffles) -> bf16 tiles ----
        #pragma unroll
        for (int bi = 0; bi < 3; bi++) {
            const int blk = nh4 * 3 + bi;   // 0..3 q heads, 4..7 k heads, 8..11 v heads
            const int jj0 = bi * 2;
            #pragma unroll
            for (int mf = 0; mf < 2; mf++) {
                float tv[2][4];
                #pragma unroll
                for (int jj = 0; jj < 2; jj++) {
                    int nl = nh4 * 48 + (jj0 + jj) * 8 + tq;
                    int gcol = (nl >> 6) * 256 + p * 64 + (nl & 63);
                    float b0 = qkv_b[gcol], b1 = qkv_b[gcol + 1];
                    int ai = (mf * 6 + jj0 + jj) * 4;
                    tv[jj][0] = acc[ai + 0] + b0;
                    tv[jj][1] = acc[ai + 1] + b1;
                    tv[jj][2] = acc[ai + 2] + b0;
                    tv[jj][3] = acc[ai + 3] + b1;
                }
                if (blk < 8) {
                    float s0 = tv[0][0]*tv[0][0] + tv[0][1]*tv[0][1]
                             + tv[1][0]*tv[1][0] + tv[1][1]*tv[1][1];
                    float s1 = tv[0][2]*tv[0][2] + tv[0][3]*tv[0][3]
                             + tv[1][2]*tv[1][2] + tv[1][3]*tv[1][3];
                    s0 += __shfl_xor_sync(0xffffffffu, s0, 1);
                    s0 += __shfl_xor_sync(0xffffffffu, s0, 2);
                    s1 += __shfl_xor_sync(0xffffffffu, s1, 1);
                    s1 += __shfl_xor_sync(0xffffffffu, s1, 2);
                    float r0s = 1.f / fmaxf(sqrtf(s0), 1e-12f);
                    float r1s = 1.f / fmaxf(sqrtf(s1), 1e-12f);
                    int head = blk & 3;
                    uint32_t base = (blk < 4) ? qt_b : kt_b;
                    stsm4(base + (((head * 64 + m0 + mf * 16 + lane15) * PQK + lhi8) << 1),
                          pack2(tv[0][0] * r0s, tv[0][1] * r0s),
                          pack2(tv[0][2] * r1s, tv[0][3] * r1s),
                          pack2(tv[1][0] * r0s, tv[1][1] * r0s),
                          pack2(tv[1][2] * r1s, tv[1][3] * r1s));
                } else {
                    int hv = blk - 8;
                    int rl = m0 + mf * 16 + g, rh = rl + 8;
                    #pragma unroll
                    for (int jj = 0; jj < 2; jj++) {
                        int dv = jj * 8 + tq;
                        uint16_t* vp = s_vt + (hv * 16 + dv) * PVT;
                        vp[rl]       = bfr(tv[jj][0]);
                        vp[PVT + rl] = bfr(tv[jj][1]);
                        vp[rh]       = bfr(tv[jj][2]);
                        vp[PVT + rh] = bfr(tv[jj][3]);
                    }
                }
            }
        }
        __syncthreads();

        // ---- HMMA attention: warp -> (head wh, row-half mh) ----
        {
            const int wh = warp >> 1, mh = warp & 1;
            const uint2* gbf = g_biasf + ((p * 4 + wh) * 4) * 256 + lane;

            uint32_t kb0[8], kb1[8];
            #pragma unroll
            for (int jp = 0; jp < 4; jp++) {
                uint32_t r[4];
                ldsm4(r, kt_b + (((wh * 64 + jp * 16 + brow) * PQK + bk) << 1));
                kb0[2 * jp] = r[0]; kb1[2 * jp] = r[1];
                kb0[2 * jp + 1] = r[2]; kb1[2 * jp + 1] = r[3];
            }
            uint32_t vb0[4][2], vb1[4][2];
            #pragma unroll
            for (int ks = 0; ks < 4; ks++) {
                uint32_t r[4];
                ldsm4(r, vt_b + (((wh * 16 + brow) * PVT + ks * 16 + bk) << 1));
                vb0[ks][0] = r[0]; vb1[ks][0] = r[1];
                vb0[ks][1] = r[2]; vb1[ks][1] = r[3];
            }

            #pragma unroll
            for (int t = 0; t < 2; t++) {
                int r = mh * 32 + t * 16;
                // fragment-layout bias: 8 coalesced LDG.64, issued first
                uint2 bfj[8];
                #pragma unroll
                for (int j = 0; j < 8; j++)
                    bfj[j] = __ldg(gbf + ((mh * 2 + t) * 8 + j) * 32);

                uint32_t qa[4];
                ldsm4(qa, qt_b + (((wh * 64 + r + lane15) * PQK + lhi8) << 1));

                float Sc[8][4];
                #pragma unroll
                for (int j = 0; j < 8; j++) {
                    float2 f0 = unpack2(bfj[j].x);
                    float2 f1 = unpack2(bfj[j].y);
                    Sc[j][0] = f0.x; Sc[j][1] = f0.y;
                    Sc[j][2] = f1.x; Sc[j][3] = f1.y;
                }
                #pragma unroll
                for (int j = 0; j < 8; j++)
                    mma16816(Sc[j], qa[0], qa[1], qa[2], qa[3], kb0[j], kb1[j]);

                float su0 = 0.f, su1 = 0.f;
                #pragma unroll
                for (int j = 0; j < 8; j++) {
                    Sc[j][0] = __expf(Sc[j][0]);
                    Sc[j][1] = __expf(Sc[j][1]);
                    Sc[j][2] = __expf(Sc[j][2]);
                    Sc[j][3] = __expf(Sc[j][3]);
                    su0 += Sc[j][0] + Sc[j][1];
                    su1 += Sc[j][2] + Sc[j][3];
                }
                su0 += __shfl_xor_sync(0xffffffffu, su0, 1);
                su0 += __shfl_xor_sync(0xffffffffu, su0, 2);
                su1 += __shfl_xor_sync(0xffffffffu, su1, 1);
                su1 += __shfl_xor_sync(0xffffffffu, su1, 2);
                float inv0 = 1.f / su0, inv1 = 1.f / su1;

                float Oc[2][4];
                #pragma unroll
                for (int nt = 0; nt < 2; nt++)
                    #pragma unroll
                    for (int i = 0; i < 4; i++) Oc[nt][i] = 0.f;

                #pragma unroll
                for (int ks = 0; ks < 4; ks++) {
                    uint32_t pa0 = pack2(Sc[2 * ks][0] * inv0,     Sc[2 * ks][1] * inv0);
                    uint32_t pa1 = pack2(Sc[2 * ks][2] * inv1,     Sc[2 * ks][3] * inv1);
                    uint32_t pa2 = pack2(Sc[2 * ks + 1][0] * inv0, Sc[2 * ks + 1][1] * inv0);
                    uint32_t pa3 = pack2(Sc[2 * ks + 1][2] * inv1, Sc[2 * ks + 1][3] * inv1);
                    #pragma unroll
                    for (int nt = 0; nt < 2; nt++)
                        mma16816(Oc[nt], pa0, pa1, pa2, pa3, vb0[ks][nt], vb1[ks][nt]);
                }

                int hc = (p * 4 + wh) * 16;
                stsm4(ab_b + (((r + lane15) * PA + hc + lhi8) << 1),
                      pack2(Oc[0][0], Oc[0][1]), pack2(Oc[0][2], Oc[0][3]),
                      pack2(Oc[1][0], Oc[1][1]), pack2(Oc[1][2], Oc[1][3]));
            }
        }
        __syncthreads();
    }

    // ---------- phase 3: proj HMMA (B fragments from L2, pipelined, zero-sync) ----------
    float acc[64];
    #pragma unroll
    for (int i = 0; i < 64; i++) acc[i] = 0.f;

    {
        uint2 B[2][8];
        #pragma unroll
        for (int j = 0; j < 8; j++)
            B[0][j] = __ldg(g_wpf + ((0 * 4 + nh4) * 8 + j) * 32 + lane);

        #pragma unroll 2
        for (int kb = 0; kb < 16; kb++) {
            if (kb < 15) {
                #pragma unroll
                for (int j = 0; j < 8; j++)
                    B[(kb + 1) & 1][j] =
                        __ldg(g_wpf + (((kb + 1) * 4 + nh4) * 8 + j) * 32 + lane);
            }
            uint32_t Af[2][4];
            #pragma unroll
            for (int mf = 0; mf < 2; mf++)
                ldsm4(Af[mf], ab_b + (((m0 + mf * 16 + lane15) * PA + kb * 16 + lhi8) << 1));
            #pragma unroll
            for (int mf = 0; mf < 2; mf++)
                #pragma unroll
                for (int j = 0; j < 8; j++)
                    mma16816(&acc[(mf * 8 + j) * 4],
                             Af[mf][0], Af[mf][1], Af[mf][2], Af[mf][3],
                             B[kb & 1][j].x, B[kb & 1][j].y);
        }
    }

    // ---------- phase 4: t = proj + bias + x (regs); post-LN; scatter out ----------
    {
        int rows[4], xo[4];
        #pragma unroll
        for (int mf = 0; mf < 2; mf++) {
            rows[mf * 2 + 0] = m0 + mf * 16 + g;
            rows[mf * 2 + 1] = m0 + mf * 16 + g + 8;
        }
        #pragma unroll
        for (int i = 0; i < 4; i++) xo[i] = (rows[i] >> 3) * 256 + (rows[i] & 7);

        float rs[4], rs2[4];
        #pragma unroll
        for (int i = 0; i < 4; i++) { rs[i] = 0.f; rs2[i] = 0.f; }

        #pragma unroll
        for (int mf = 0; mf < 2; mf++)
            #pragma unroll
            for (int j = 0; j < 8; j++) {
                int c = nh4 * 64 + j * 8 + tq;
                int ai = (mf * 8 + j) * 4;
                float pb0 = proj_b[c], pb1 = proj_b[c + 1];
                acc[ai + 0] += pb0 + Xb[(size_t)c * 65536 + xo[mf * 2]];
                acc[ai + 1] += pb1 + Xb[(size_t)(c + 1) * 65536 + xo[mf * 2]];
                acc[ai + 2] += pb0 + Xb[(size_t)c * 65536 + xo[mf * 2 + 1]];
                acc[ai + 3] += pb1 + Xb[(size_t)(c + 1) * 65536 + xo[mf * 2 + 1]];
                rs[mf * 2]      += acc[ai + 0] + acc[ai + 1];
                rs2[mf * 2]     += acc[ai + 0] * acc[ai + 0] + acc[ai + 1] * acc[ai + 1];
                rs[mf * 2 + 1]  += acc[ai + 2] + acc[ai + 3];
                rs2[mf * 2 + 1] += acc[ai + 2] * acc[ai + 2] + acc[ai + 3] * acc[ai + 3];
            }
        #pragma unroll
        for (int i = 0; i < 4; i++) {
            rs[i]  += __shfl_xor_sync(0xffffffffu, rs[i], 1);
            rs[i]  += __shfl_xor_sync(0xffffffffu, rs[i], 2);
            rs2[i] += __shfl_xor_sync(0xffffffffu, rs2[i], 1);
            rs2[i] += __shfl_xor_sync(0xffffffffu, rs2[i], 2);
        }
        if (tq == 0) {
            #pragma unroll
            for (int i = 0; i < 4; i++)
                s_red[rows[i]][nh4] = make_float2(rs[i], rs2[i]);
        }
        __syncthreads();
        if (tid < 64) {
            float ts = 0.f, ts2 = 0.f;
            #pragma unroll
            for (int q4 = 0; q4 < 4; q4++) {
                float2 a = s_red[tid][q4];
                ts += a.x; ts2 += a.y;
            }
            float mean = ts * (1.f / 256.f);
            s_m[tid] = mean;
            s_i[tid] = rsqrtf(ts2 * (1.f / 256.f) - mean * mean + 1e-5f);
        }
        __syncthreads();

        float mm[4], ii[4];
        #pragma unroll
        for (int i = 0; i < 4; i++) { mm[i] = s_m[rows[i]]; ii[i] = s_i[rows[i]]; }

        #pragma unroll
        for (int mf = 0; mf < 2; mf++)
            #pragma unroll
            for (int j = 0; j < 8; j++) {
                int c = nh4 * 64 + j * 8 + tq;
                int ai = (mf * 8 + j) * 4;
                float pg0 = post_g[c], pg1 = post_g[c + 1];
                float pbb0 = post_b[c], pbb1 = post_b[c + 1];
                int rlo = mf * 2, rhi = mf * 2 + 1;
                float t00 = acc[ai + 0], t01 = acc[ai + 1];
                float t10 = acc[ai + 2], t11 = acc[ai + 3];
                Ob[(size_t)c * 65536 + xo[rlo]]       = t00 + (t00 - mm[rlo]) * ii[rlo] * pg0 + pbb0;
                Ob[(size_t)(c + 1) * 65536 + xo[rlo]] = t01 + (t01 - mm[rlo]) * ii[rlo] * pg1 + pbb1;
                Ob[(size_t)c * 65536 + xo[rhi]]       = t10 + (t10 - mm[rhi]) * ii[rhi] * pg0 + pbb0;
                Ob[(size_t)(c + 1) * 65536 + xo[rhi]] = t11 + (t11 - mm[rhi]) * ii[rhi] * pg1 + pbb1;
            }
    }
}

extern "C" void kernel_launch(void* const* d_in, const int* in_sizes, int n_in,
                              void* d_out, int out_size) {
    const float* X      = (const float*)d_in[0];
    const float* pre_g  = (const float*)d_in[1];
    const float* pre_b  = (const float*)d_in[2];
    const float* post_g = (const float*)d_in[3];
    const float* post_b = (const float*)d_in[4];
    const float* qkv_w  = (const float*)d_in[5];
    const float* qkv_b  = (const float*)d_in[6];
    const float* proj_w = (const float*)d_in[7];
    const float* proj_b = (const float*)d_in[8];
    const float* rtab   = (const float*)d_in[9];
    const int*   ridx   = (const int*)d_in[10];
    float* out = (float*)d_out;

    const int smem_bytes = SMEM_FLOATS * 4;   // 103,936 B -> 2 CTAs/SM
    cudaFuncSetAttribute(window_attn_kernel,
                         cudaFuncAttributeMaxDynamicSharedMemorySize, smem_bytes);

    prep_bias_frag<<<64, 256>>>(rtab, ridx);
    prep_wq_frag<<<192, 256>>>(qkv_w);
    prep_wp_frag<<<64, 256>>>(proj_w);
    window_attn_kernel<<<2048, 256, smem_bytes>>>(
        X, pre_g, pre_b, post_g, post_b, qkv_b, proj_b, out);
}